// round 1
// baseline (speedup 1.0000x reference)
#include <cuda_runtime.h>
#include <math.h>

// Problem constants: B=4, S=2048, Hd=1024, H=8, dk=128, wA=67
#define NBH   32           // B*H
#define SEQ   2048
#define DKD   128
#define WAW   67
#define OUT1_ELEMS (4*2048*536)   // B*S*(H*wA)

// ---------------- scratch (static device globals; no allocation) ----------------
__device__ float g_Q[NBH*SEQ*DKD];   // (b,h,s,d), pre-scaled by dk^-0.5
__device__ float g_K[NBH*SEQ*DKD];
__device__ float g_V[NBH*SEQ*DKD];
__device__ float g_cD[NBH*SEQ*WAW];  // (b,h,s,w)

__constant__ float c_lo[8] = { -0.010597401784997278f, 0.032883011666982945f,
                                0.030841381835986965f, -0.18703481171888114f,
                               -0.02798376941698385f,  0.6308807679295904f,
                                0.7148465705525415f,   0.23037781330885523f };
__constant__ float c_hi[8] = { -0.23037781330885523f,  0.7148465705525415f,
                               -0.6308807679295904f,  -0.02798376941698385f,
                                0.18703481171888114f,  0.030841381835986965f,
                               -0.032883011666982945f, -0.010597401784997278f };

// ======================================================================
// Kernel 1: fused QKV projection.  C = x @ W^T  (NT GEMM, both K-major)
// Tile 128(M) x 128(N) x 32(K), 256 threads, 8x8 micro-tile.
// SMEM k-major with XOR swizzle: element (kk,m) stored at column
// group (m>>2) ^ (kk>>2) -> transposed scalar stores AND float4 compute
// loads are both bank-conflict-free.
// ======================================================================
__global__ __launch_bounds__(256) void qkv_kernel(
    const float* __restrict__ x, const float* __restrict__ Wq,
    const float* __restrict__ Wk, const float* __restrict__ Wv)
{
    __shared__ float As[32*128];
    __shared__ float Bs[32*128];

    const int tid = threadIdx.x;
    const int tx = tid & 15, ty = tid >> 4;
    const int which = blockIdx.z;
    const float* W = (which == 0) ? Wq : ((which == 1) ? Wk : Wv);
    float* O       = (which == 0) ? g_Q : ((which == 1) ? g_K : g_V);
    const float scale = (which == 0) ? 0.08838834764831845f : 1.0f; // 128^-0.5

    const int m0 = blockIdx.y * 128;
    const int h  = blockIdx.x;            // N tile == head index (128 cols per head)
    const float* xb = x + (size_t)m0 * 1024;
    const float* wb = W + (size_t)h * 128 * 1024;

    float c[8][8];
#pragma unroll
    for (int i = 0; i < 8; i++)
#pragma unroll
        for (int j = 0; j < 8; j++) c[i][j] = 0.0f;

    for (int kb = 0; kb < 1024; kb += 32) {
#pragma unroll
        for (int u = 0; u < 4; u++) {
            const int idx = tid + 256*u;
            const int m = idx >> 3, kg = idx & 7;       // row, k-group(of 4)
            const float4 a4 = *(const float4*)(xb + (size_t)m*1024 + kb + kg*4);
            const float4 b4 = *(const float4*)(wb + (size_t)m*1024 + kb + kg*4);
            const int col = (((m >> 2) ^ kg) << 2) + (m & 3);   // swizzled col
            As[(kg*4+0)*128 + col] = a4.x;
            As[(kg*4+1)*128 + col] = a4.y;
            As[(kg*4+2)*128 + col] = a4.z;
            As[(kg*4+3)*128 + col] = a4.w;
            Bs[(kg*4+0)*128 + col] = b4.x;
            Bs[(kg*4+1)*128 + col] = b4.y;
            Bs[(kg*4+2)*128 + col] = b4.z;
            Bs[(kg*4+3)*128 + col] = b4.w;
        }
        __syncthreads();

#pragma unroll 8
        for (int kk = 0; kk < 32; kk++) {
            const int sw = kk >> 2;
            const float4 a0 = *(const float4*)&As[kk*128 + ((((ty<<1)   ) ^ sw) << 2)];
            const float4 a1 = *(const float4*)&As[kk*128 + ((((ty<<1)|1 ) ^ sw) << 2)];
            const float4 b0 = *(const float4*)&Bs[kk*128 + (((tx      ) ^ sw) << 2)];
            const float4 b1 = *(const float4*)&Bs[kk*128 + (((tx + 16 ) ^ sw) << 2)];
            const float av[8] = {a0.x,a0.y,a0.z,a0.w, a1.x,a1.y,a1.z,a1.w};
            const float bv[8] = {b0.x,b0.y,b0.z,b0.w, b1.x,b1.y,b1.z,b1.w};
#pragma unroll
            for (int i = 0; i < 8; i++)
#pragma unroll
                for (int j = 0; j < 8; j++)
                    c[i][j] = fmaf(av[i], bv[j], c[i][j]);
        }
        __syncthreads();
    }

    // Epilogue: write into (b,h,s,d) layout. Cols: tx*4..+3 and 64+tx*4..+3.
#pragma unroll
    for (int i = 0; i < 8; i++) {
        const int m = m0 + ty*8 + i;
        const int b = m >> 11, sq = m & 2047;
        float* dst = O + (((size_t)(b*8 + h) * 2048 + sq) << 7);
        float4 v0 = make_float4(c[i][0]*scale, c[i][1]*scale, c[i][2]*scale, c[i][3]*scale);
        float4 v1 = make_float4(c[i][4]*scale, c[i][5]*scale, c[i][6]*scale, c[i][7]*scale);
        *(float4*)(dst + tx*4)      = v0;
        *(float4*)(dst + 64 + tx*4) = v1;
    }
}

// ======================================================================
// Kernel 2: db4 DWT along dk=128 (symmetric half-point extension).
// ext1(j), j in [0,140]:  j<6 -> x[5-j]; j<134 -> x[j-6]; else x[261-j]
// cA -> out2 region of d_out (raw (b,h,s,w) order), cD -> scratch.
// ======================================================================
__global__ __launch_bounds__(128) void dwt_kernel(float* __restrict__ out2)
{
    const int rowid = blockIdx.x;     // bh*2048 + s
    __shared__ float v[DKD];
    const int t = threadIdx.x;
    v[t] = g_V[(size_t)rowid * DKD + t];
    __syncthreads();
    if (t < WAW) {
        float a = 0.0f, d = 0.0f;
#pragma unroll
        for (int k = 0; k < 8; k++) {
            const int j = 2*t + k;
            const int src = (j < 6) ? (5 - j) : ((j < 134) ? (j - 6) : (261 - j));
            const float e = v[src];
            a = fmaf(e, c_lo[7 - k], a);
            d = fmaf(e, c_hi[7 - k], d);
        }
        out2[(size_t)rowid * WAW + t] = a;
        g_cD[(size_t)rowid * WAW + t] = d;
    }
}

// ======================================================================
// Kernel 3: flash attention fused with (attn @ cD).
// Block: one (b,h) head, 64 queries. Stream 64-key tiles, online softmax.
// SMEM: Qs/Ks k-major 128x64 XOR-swizzled; cD tile [64][68]; P tile [64][68].
// S-phase: 16x16 threads, 4x4 micro. PV-phase: 4 threads/row x 17 cols.
// ======================================================================
__global__ __launch_bounds__(256, 2) void flash_kernel(float* __restrict__ out1)
{
    extern __shared__ float sm[];
    float* Qs   = sm;                 // 128*64
    float* Ks   = sm + 8192;          // 128*64
    float* cDs  = sm + 16384;         // 64*68
    float* Ps   = sm + 16384 + 4352;  // 64*68
    float* m_s  = Ps + 4352;          // 64
    float* l_s  = m_s + 64;           // 64
    float* al_s = l_s + 64;           // 64

    const int tid = threadIdx.x;
    const int tx = tid & 15, ty = tid >> 4;       // S-phase mapping
    const int row2 = tid >> 2, g = tid & 3;       // PV-phase mapping
    const int bh = blockIdx.y;
    const int q0 = blockIdx.x * 64;

    const float* Qg  = g_Q  + (size_t)bh * SEQ * DKD;
    const float* Kg  = g_K  + (size_t)bh * SEQ * DKD;
    const float* cDg = g_cD + (size_t)bh * SEQ * WAW;

    // Load Q tile (64 rows x 128 d) into swizzled k-major SMEM
#pragma unroll
    for (int u = 0; u < 8; u++) {
        const int idx = tid + 256*u;
        const int r = idx >> 5, dg = idx & 31;
        const float4 q4 = *(const float4*)(Qg + (size_t)(q0 + r)*DKD + dg*4);
        const int col = (((r >> 2) ^ (dg & 15)) << 2) + (r & 3);
        Qs[(dg*4+0)*64 + col] = q4.x;
        Qs[(dg*4+1)*64 + col] = q4.y;
        Qs[(dg*4+2)*64 + col] = q4.z;
        Qs[(dg*4+3)*64 + col] = q4.w;
    }
    if (tid < 64) { m_s[tid] = -1e30f; l_s[tid] = 0.0f; }

    float4 acc0 = make_float4(0,0,0,0), acc1 = acc0, acc2 = acc0, acc3 = acc0;
    float accE = 0.0f;
    __syncthreads();

    for (int nt = 0; nt < 32; nt++) {
        const int n0 = nt * 64;
        // load K tile
#pragma unroll
        for (int u = 0; u < 8; u++) {
            const int idx = tid + 256*u;
            const int r = idx >> 5, dg = idx & 31;
            const float4 k4 = *(const float4*)(Kg + (size_t)(n0 + r)*DKD + dg*4);
            const int col = (((r >> 2) ^ (dg & 15)) << 2) + (r & 3);
            Ks[(dg*4+0)*64 + col] = k4.x;
            Ks[(dg*4+1)*64 + col] = k4.y;
            Ks[(dg*4+2)*64 + col] = k4.z;
            Ks[(dg*4+3)*64 + col] = k4.w;
        }
        // load cD tile [64][67] -> [64][68] padded (64*68 = 17*256 exactly)
#pragma unroll
        for (int u = 0; u < 17; u++) {
            const int idx = tid + 256*u;
            const int j = idx / 68;
            const int w = idx - j*68;
            cDs[idx] = (w < WAW) ? cDg[(size_t)(n0 + j)*WAW + w] : 0.0f;
        }
        __syncthreads();

        // ---- S = Q K^T (64x64 tile) ----
        float s[4][4];
#pragma unroll
        for (int i = 0; i < 4; i++)
#pragma unroll
            for (int j = 0; j < 4; j++) s[i][j] = 0.0f;

#pragma unroll 16
        for (int kk = 0; kk < 128; kk++) {
            const int sw = (kk >> 2) & 15;
            const float4 a = *(const float4*)&Qs[kk*64 + ((ty ^ sw) << 2)];
            const float4 b = *(const float4*)&Ks[kk*64 + ((tx ^ sw) << 2)];
            const float av[4] = {a.x, a.y, a.z, a.w};
            const float bv[4] = {b.x, b.y, b.z, b.w};
#pragma unroll
            for (int i = 0; i < 4; i++)
#pragma unroll
                for (int j = 0; j < 4; j++)
                    s[i][j] = fmaf(av[i], bv[j], s[i][j]);
        }

        // ---- online softmax: rows ty*4+i, reduce over tx (16-lane groups) ----
#pragma unroll
        for (int i = 0; i < 4; i++) {
            const int r = ty*4 + i;
            float mx = fmaxf(fmaxf(s[i][0], s[i][1]), fmaxf(s[i][2], s[i][3]));
#pragma unroll
            for (int o = 8; o >= 1; o >>= 1)
                mx = fmaxf(mx, __shfl_xor_sync(0xffffffffu, mx, o, 16));
            const float mo = m_s[r];
            const float mn = fmaxf(mo, mx);
            float4 p;
            p.x = __expf(s[i][0] - mn);
            p.y = __expf(s[i][1] - mn);
            p.z = __expf(s[i][2] - mn);
            p.w = __expf(s[i][3] - mn);
            float ps = (p.x + p.y) + (p.z + p.w);
#pragma unroll
            for (int o = 8; o >= 1; o >>= 1)
                ps += __shfl_xor_sync(0xffffffffu, ps, o, 16);
            *(float4*)&Ps[r*68 + tx*4] = p;
            if (tx == 0) {
                const float al = __expf(mo - mn);
                al_s[r] = al;
                l_s[r] = l_s[r]*al + ps;
                m_s[r] = mn;
            }
        }
        __syncthreads();

        // ---- PV: acc(row2, cols g*16..+15 and 64+g) += P[row2][:] @ cD ----
        {
            const float alpha = al_s[row2];
            acc0.x*=alpha; acc0.y*=alpha; acc0.z*=alpha; acc0.w*=alpha;
            acc1.x*=alpha; acc1.y*=alpha; acc1.z*=alpha; acc1.w*=alpha;
            acc2.x*=alpha; acc2.y*=alpha; acc2.z*=alpha; acc2.w*=alpha;
            acc3.x*=alpha; acc3.y*=alpha; acc3.z*=alpha; acc3.w*=alpha;
            accE *= alpha;
            const float* prow = &Ps[row2*68];
#pragma unroll 8
            for (int j = 0; j < 64; j++) {
                const float p = prow[j];
                const float* crow = cDs + j*68 + g*16;
                const float4 c0 = *(const float4*)(crow + 0);
                const float4 c1 = *(const float4*)(crow + 4);
                const float4 c2 = *(const float4*)(crow + 8);
                const float4 c3 = *(const float4*)(crow + 12);
                acc0.x=fmaf(p,c0.x,acc0.x); acc0.y=fmaf(p,c0.y,acc0.y);
                acc0.z=fmaf(p,c0.z,acc0.z); acc0.w=fmaf(p,c0.w,acc0.w);
                acc1.x=fmaf(p,c1.x,acc1.x); acc1.y=fmaf(p,c1.y,acc1.y);
                acc1.z=fmaf(p,c1.z,acc1.z); acc1.w=fmaf(p,c1.w,acc1.w);
                acc2.x=fmaf(p,c2.x,acc2.x); acc2.y=fmaf(p,c2.y,acc2.y);
                acc2.z=fmaf(p,c2.z,acc2.z); acc2.w=fmaf(p,c2.w,acc2.w);
                acc3.x=fmaf(p,c3.x,acc3.x); acc3.y=fmaf(p,c3.y,acc3.y);
                acc3.z=fmaf(p,c3.z,acc3.z); acc3.w=fmaf(p,c3.w,acc3.w);
                accE = fmaf(p, cDs[j*68 + 64 + g], accE);
            }
        }
        __syncthreads();
    }

    // ---- epilogue: divide by l, write out1[b][q0+row2][h*67 + col] ----
    const float inv = 1.0f / l_s[row2];
    const int b = bh >> 3, h = bh & 7;
    const size_t base = (size_t)(b*2048 + q0 + row2) * 536 + h*67;
    float av_[16] = {acc0.x,acc0.y,acc0.z,acc0.w, acc1.x,acc1.y,acc1.z,acc1.w,
                     acc2.x,acc2.y,acc2.z,acc2.w, acc3.x,acc3.y,acc3.z,acc3.w};
    float* orow = out1 + base + g*16;
#pragma unroll
    for (int q = 0; q < 16; q++) orow[q] = av_[q] * inv;
    if (g < 3) out1[base + 64 + g] = accE * inv;
}

// ======================================================================
extern "C" void kernel_launch(void* const* d_in, const int* in_sizes, int n_in,
                              void* d_out, int out_size)
{
    (void)in_sizes; (void)n_in; (void)out_size;
    const float* x  = (const float*)d_in[0];
    const float* Wq = (const float*)d_in[1];
    const float* Wk = (const float*)d_in[2];
    const float* Wv = (const float*)d_in[3];
    float* out = (float*)d_out;

    qkv_kernel<<<dim3(8, 64, 3), 256>>>(x, Wq, Wk, Wv);
    dwt_kernel<<<NBH * SEQ, 128>>>(out + OUT1_ELEMS);

    cudaFuncSetAttribute(flash_kernel, cudaFuncAttributeMaxDynamicSharedMemorySize,
                         101120);
    flash_kernel<<<dim3(32, 32), 256, 101120>>>(out);
}

// round 3
// speedup vs baseline: 1.2316x; 1.2316x over previous
#include <cuda_runtime.h>
#include <math.h>
#include <cstdint>

// Problem constants: B=4, S=2048, Hd=1024, H=8, dk=128, wA=67
#define NBH   32           // B*H
#define SEQ   2048
#define DKD   128
#define WAW   67
#define OUT1_ELEMS (4*2048*536)   // B*S*(H*wA)

// ---------------- scratch (static device globals; no allocation) ----------------
__device__ float g_Q[NBH*SEQ*DKD];   // (b,h,s,d), pre-scaled by dk^-0.5
__device__ float g_K[NBH*SEQ*DKD];
__device__ float g_V[NBH*SEQ*DKD];
__device__ float g_cD[NBH*SEQ*WAW];  // (b,h,s,w)

__constant__ float c_lo[8] = { -0.010597401784997278f, 0.032883011666982945f,
                                0.030841381835986965f, -0.18703481171888114f,
                               -0.02798376941698385f,  0.6308807679295904f,
                                0.7148465705525415f,   0.23037781330885523f };
__constant__ float c_hi[8] = { -0.23037781330885523f,  0.7148465705525415f,
                               -0.6308807679295904f,  -0.02798376941698385f,
                                0.18703481171888114f,  0.030841381835986965f,
                               -0.032883011666982945f, -0.010597401784997278f };

__device__ __forceinline__ uint32_t f2tf32(float f) {
    uint32_t u;
    asm("cvt.rna.tf32.f32 %0, %1;" : "=r"(u) : "f"(f));
    return u;
}

__device__ __forceinline__ void mma_tf32(float& d0, float& d1, float& d2, float& d3,
                                         uint32_t a0, uint32_t a1, uint32_t a2, uint32_t a3,
                                         uint32_t b0, uint32_t b1) {
    asm volatile(
        "mma.sync.aligned.m16n8k8.row.col.f32.tf32.tf32.f32 "
        "{%0,%1,%2,%3}, {%4,%5,%6,%7}, {%8,%9}, {%0,%1,%2,%3};"
        : "+f"(d0), "+f"(d1), "+f"(d2), "+f"(d3)
        : "r"(a0), "r"(a1), "r"(a2), "r"(a3), "r"(b0), "r"(b1));
}

// ======================================================================
// Kernel 1: QKV projection via mma.sync tf32.  C = x @ W^T  (NT GEMM).
// CTA tile 128(M) x 128(N=one head) x K1024, chunk 32, double-buffered.
// 8 warps: 4(M) x 2(N); warp tile 32x64 = 2x8 m16n8k8 fragments.
// SMEM row stride 36 (=4 mod 32) -> fragment LDS bank-conflict-free.
// ======================================================================
#define CHN 4608            // 128*36 floats per buffer
#define QKV_SMEM (4*CHN*4)  // As[2] + Bs[2] = 73728 bytes

__global__ __launch_bounds__(256) void qkv_mma_kernel(
    const float* __restrict__ x, const float* __restrict__ Wq,
    const float* __restrict__ Wk, const float* __restrict__ Wv)
{
    extern __shared__ float sm[];
    float* As = sm;             // [2][128][36]
    float* Bs = sm + 2*CHN;     // [2][128][36]

    const int tid  = threadIdx.x;
    const int lane = tid & 31;
    const int warp = tid >> 5;
    const int g    = lane >> 2;         // 0..7
    const int tig  = lane & 3;          // 0..3
    const int wm   = warp & 3;          // M warp (rows wm*32)
    const int wn   = warp >> 2;         // N warp (cols wn*64)

    const int which = blockIdx.z;
    const float* W = (which == 0) ? Wq : ((which == 1) ? Wk : Wv);
    float* O       = (which == 0) ? g_Q : ((which == 1) ? g_K : g_V);
    const float scale = (which == 0) ? 0.08838834764831845f : 1.0f;

    const int m0   = blockIdx.y * 128;
    const int head = blockIdx.x;                  // N tile == head (128 cols)
    const float* xb = x + (size_t)m0 * 1024;
    const float* wb = W + (size_t)head * 128 * 1024;

    // per-thread gmem load coords (4 float4 each for A and B per chunk)
    const int lr = tid >> 3;        // row 0..31 step: +32 per u
    const int lc = (tid & 7) * 4;   // k offset 0..28

    float c[2][8][4];
#pragma unroll
    for (int mt = 0; mt < 2; mt++)
#pragma unroll
        for (int nt = 0; nt < 8; nt++)
#pragma unroll
            for (int q = 0; q < 4; q++) c[mt][nt][q] = 0.0f;

    // ---- preload chunk 0 ----
    {
#pragma unroll
        for (int u = 0; u < 4; u++) {
            const int r = lr + 32*u;
            const float4 a4 = *(const float4*)(xb + (size_t)r*1024 + lc);
            const float4 b4 = *(const float4*)(wb + (size_t)r*1024 + lc);
            float* pa = As + r*36 + lc;
            float* pb = Bs + r*36 + lc;
            pa[0] = __uint_as_float(f2tf32(a4.x)); pa[1] = __uint_as_float(f2tf32(a4.y));
            pa[2] = __uint_as_float(f2tf32(a4.z)); pa[3] = __uint_as_float(f2tf32(a4.w));
            pb[0] = __uint_as_float(f2tf32(b4.x)); pb[1] = __uint_as_float(f2tf32(b4.y));
            pb[2] = __uint_as_float(f2tf32(b4.z)); pb[3] = __uint_as_float(f2tf32(b4.w));
        }
    }
    __syncthreads();

    for (int ch = 0; ch < 32; ch++) {
        const int cur = ch & 1;
        float4 pfa[4], pfb[4];
        if (ch < 31) {
            const int kb = (ch + 1) << 5;
#pragma unroll
            for (int u = 0; u < 4; u++) {
                const int r = lr + 32*u;
                pfa[u] = *(const float4*)(xb + (size_t)r*1024 + kb + lc);
                pfb[u] = *(const float4*)(wb + (size_t)r*1024 + kb + lc);
            }
        }

        const float* as = As + cur*CHN;
        const float* bs = Bs + cur*CHN;
#pragma unroll
        for (int ks = 0; ks < 4; ks++) {
            const int k0 = ks * 8;
            uint32_t a[2][4];
#pragma unroll
            for (int mt = 0; mt < 2; mt++) {
                const int rb = wm*32 + mt*16 + g;
                a[mt][0] = __float_as_uint(as[(rb    )*36 + k0 + tig]);
                a[mt][1] = __float_as_uint(as[(rb + 8)*36 + k0 + tig]);
                a[mt][2] = __float_as_uint(as[(rb    )*36 + k0 + tig + 4]);
                a[mt][3] = __float_as_uint(as[(rb + 8)*36 + k0 + tig + 4]);
            }
#pragma unroll
            for (int nt = 0; nt < 8; nt++) {
                const int nb = wn*64 + nt*8 + g;
                const uint32_t b0 = __float_as_uint(bs[nb*36 + k0 + tig]);
                const uint32_t b1 = __float_as_uint(bs[nb*36 + k0 + tig + 4]);
#pragma unroll
                for (int mt = 0; mt < 2; mt++)
                    mma_tf32(c[mt][nt][0], c[mt][nt][1], c[mt][nt][2], c[mt][nt][3],
                             a[mt][0], a[mt][1], a[mt][2], a[mt][3], b0, b1);
            }
        }

        if (ch < 31) {
            float* pa0 = As + (cur^1)*CHN;
            float* pb0 = Bs + (cur^1)*CHN;
#pragma unroll
            for (int u = 0; u < 4; u++) {
                const int r = lr + 32*u;
                float* pa = pa0 + r*36 + lc;
                float* pb = pb0 + r*36 + lc;
                pa[0] = __uint_as_float(f2tf32(pfa[u].x)); pa[1] = __uint_as_float(f2tf32(pfa[u].y));
                pa[2] = __uint_as_float(f2tf32(pfa[u].z)); pa[3] = __uint_as_float(f2tf32(pfa[u].w));
                pb[0] = __uint_as_float(f2tf32(pfb[u].x)); pb[1] = __uint_as_float(f2tf32(pfb[u].y));
                pb[2] = __uint_as_float(f2tf32(pfb[u].z)); pb[3] = __uint_as_float(f2tf32(pfb[u].w));
            }
        }
        __syncthreads();
    }

    // ---- epilogue: write (b,h,s,d), scale for Q ----
#pragma unroll
    for (int mt = 0; mt < 2; mt++) {
        const int m  = m0 + wm*32 + mt*16 + g;
        const int b0_ = m >> 11, sq = m & 2047;
        float* dst0 = O + (((size_t)(b0_*8 + head) * 2048 + sq) << 7);
        float* dst1 = dst0 + (8 << 7);   // row m+8 (same b,head since tiles are 128-aligned)
#pragma unroll
        for (int nt = 0; nt < 8; nt++) {
            const int d = wn*64 + nt*8 + 2*tig;
            float2 v0 = make_float2(c[mt][nt][0]*scale, c[mt][nt][1]*scale);
            float2 v1 = make_float2(c[mt][nt][2]*scale, c[mt][nt][3]*scale);
            *(float2*)(dst0 + d) = v0;
            *(float2*)(dst1 + d) = v1;
        }
    }
}

// ======================================================================
// Kernel 2: db4 DWT along dk=128 (symmetric half-point extension).
// cA -> out2 region of d_out, cD -> scratch.
// ======================================================================
__global__ __launch_bounds__(128) void dwt_kernel(float* __restrict__ out2)
{
    const int rowid = blockIdx.x;     // bh*2048 + s
    __shared__ float v[DKD];
    const int t = threadIdx.x;
    v[t] = g_V[(size_t)rowid * DKD + t];
    __syncthreads();
    if (t < WAW) {
        float a = 0.0f, d = 0.0f;
#pragma unroll
        for (int k = 0; k < 8; k++) {
            const int j = 2*t + k;
            const int src = (j < 6) ? (5 - j) : ((j < 134) ? (j - 6) : (261 - j));
            const float e = v[src];
            a = fmaf(e, c_lo[7 - k], a);
            d = fmaf(e, c_hi[7 - k], d);
        }
        out2[(size_t)rowid * WAW + t] = a;
        g_cD[(size_t)rowid * WAW + t] = d;
    }
}

// ======================================================================
// Kernel 3: flash attention fused with (attn @ cD).  (fp32, unchanged)
// ======================================================================
__global__ __launch_bounds__(256, 2) void flash_kernel(float* __restrict__ out1)
{
    extern __shared__ float sm[];
    float* Qs   = sm;                 // 128*64
    float* Ks   = sm + 8192;          // 128*64
    float* cDs  = sm + 16384;         // 64*68
    float* Ps   = sm + 16384 + 4352;  // 64*68
    float* m_s  = Ps + 4352;          // 64
    float* l_s  = m_s + 64;           // 64
    float* al_s = l_s + 64;           // 64

    const int tid = threadIdx.x;
    const int tx = tid & 15, ty = tid >> 4;       // S-phase mapping
    const int row2 = tid >> 2, g = tid & 3;       // PV-phase mapping
    const int bh = blockIdx.y;
    const int q0 = blockIdx.x * 64;

    const float* Qg  = g_Q  + (size_t)bh * SEQ * DKD;
    const float* Kg  = g_K  + (size_t)bh * SEQ * DKD;
    const float* cDg = g_cD + (size_t)bh * SEQ * WAW;

#pragma unroll
    for (int u = 0; u < 8; u++) {
        const int idx = tid + 256*u;
        const int r = idx >> 5, dg = idx & 31;
        const float4 q4 = *(const float4*)(Qg + (size_t)(q0 + r)*DKD + dg*4);
        const int col = (((r >> 2) ^ (dg & 15)) << 2) + (r & 3);
        Qs[(dg*4+0)*64 + col] = q4.x;
        Qs[(dg*4+1)*64 + col] = q4.y;
        Qs[(dg*4+2)*64 + col] = q4.z;
        Qs[(dg*4+3)*64 + col] = q4.w;
    }
    if (tid < 64) { m_s[tid] = -1e30f; l_s[tid] = 0.0f; }

    float4 acc0 = make_float4(0,0,0,0), acc1 = acc0, acc2 = acc0, acc3 = acc0;
    float accE = 0.0f;
    __syncthreads();

    for (int nt = 0; nt < 32; nt++) {
        const int n0 = nt * 64;
#pragma unroll
        for (int u = 0; u < 8; u++) {
            const int idx = tid + 256*u;
            const int r = idx >> 5, dg = idx & 31;
            const float4 k4 = *(const float4*)(Kg + (size_t)(n0 + r)*DKD + dg*4);
            const int col = (((r >> 2) ^ (dg & 15)) << 2) + (r & 3);
            Ks[(dg*4+0)*64 + col] = k4.x;
            Ks[(dg*4+1)*64 + col] = k4.y;
            Ks[(dg*4+2)*64 + col] = k4.z;
            Ks[(dg*4+3)*64 + col] = k4.w;
        }
#pragma unroll
        for (int u = 0; u < 17; u++) {
            const int idx = tid + 256*u;
            const int j = idx / 68;
            const int w = idx - j*68;
            cDs[idx] = (w < WAW) ? cDg[(size_t)(n0 + j)*WAW + w] : 0.0f;
        }
        __syncthreads();

        float s[4][4];
#pragma unroll
        for (int i = 0; i < 4; i++)
#pragma unroll
            for (int j = 0; j < 4; j++) s[i][j] = 0.0f;

#pragma unroll 16
        for (int kk = 0; kk < 128; kk++) {
            const int sw = (kk >> 2) & 15;
            const float4 a = *(const float4*)&Qs[kk*64 + ((ty ^ sw) << 2)];
            const float4 b = *(const float4*)&Ks[kk*64 + ((tx ^ sw) << 2)];
            const float av[4] = {a.x, a.y, a.z, a.w};
            const float bv[4] = {b.x, b.y, b.z, b.w};
#pragma unroll
            for (int i = 0; i < 4; i++)
#pragma unroll
                for (int j = 0; j < 4; j++)
                    s[i][j] = fmaf(av[i], bv[j], s[i][j]);
        }

#pragma unroll
        for (int i = 0; i < 4; i++) {
            const int r = ty*4 + i;
            float mx = fmaxf(fmaxf(s[i][0], s[i][1]), fmaxf(s[i][2], s[i][3]));
#pragma unroll
            for (int o = 8; o >= 1; o >>= 1)
                mx = fmaxf(mx, __shfl_xor_sync(0xffffffffu, mx, o, 16));
            const float mo = m_s[r];
            const float mn = fmaxf(mo, mx);
            float4 p;
            p.x = __expf(s[i][0] - mn);
            p.y = __expf(s[i][1] - mn);
            p.z = __expf(s[i][2] - mn);
            p.w = __expf(s[i][3] - mn);
            float ps = (p.x + p.y) + (p.z + p.w);
#pragma unroll
            for (int o = 8; o >= 1; o >>= 1)
                ps += __shfl_xor_sync(0xffffffffu, ps, o, 16);
            *(float4*)&Ps[r*68 + tx*4] = p;
            if (tx == 0) {
                const float al = __expf(mo - mn);
                al_s[r] = al;
                l_s[r] = l_s[r]*al + ps;
                m_s[r] = mn;
            }
        }
        __syncthreads();

        {
            const float alpha = al_s[row2];
            acc0.x*=alpha; acc0.y*=alpha; acc0.z*=alpha; acc0.w*=alpha;
            acc1.x*=alpha; acc1.y*=alpha; acc1.z*=alpha; acc1.w*=alpha;
            acc2.x*=alpha; acc2.y*=alpha; acc2.z*=alpha; acc2.w*=alpha;
            acc3.x*=alpha; acc3.y*=alpha; acc3.z*=alpha; acc3.w*=alpha;
            accE *= alpha;
            const float* prow = &Ps[row2*68];
#pragma unroll 8
            for (int j = 0; j < 64; j++) {
                const float p = prow[j];
                const float* crow = cDs + j*68 + g*16;
                const float4 c0 = *(const float4*)(crow + 0);
                const float4 c1 = *(const float4*)(crow + 4);
                const float4 c2 = *(const float4*)(crow + 8);
                const float4 c3 = *(const float4*)(crow + 12);
                acc0.x=fmaf(p,c0.x,acc0.x); acc0.y=fmaf(p,c0.y,acc0.y);
                acc0.z=fmaf(p,c0.z,acc0.z); acc0.w=fmaf(p,c0.w,acc0.w);
                acc1.x=fmaf(p,c1.x,acc1.x); acc1.y=fmaf(p,c1.y,acc1.y);
                acc1.z=fmaf(p,c1.z,acc1.z); acc1.w=fmaf(p,c1.w,acc1.w);
                acc2.x=fmaf(p,c2.x,acc2.x); acc2.y=fmaf(p,c2.y,acc2.y);
                acc2.z=fmaf(p,c2.z,acc2.z); acc2.w=fmaf(p,c2.w,acc2.w);
                acc3.x=fmaf(p,c3.x,acc3.x); acc3.y=fmaf(p,c3.y,acc3.y);
                acc3.z=fmaf(p,c3.z,acc3.z); acc3.w=fmaf(p,c3.w,acc3.w);
                accE = fmaf(p, cDs[j*68 + 64 + g], accE);
            }
        }
        __syncthreads();
    }

    const float inv = 1.0f / l_s[row2];
    const int b = bh >> 3, h = bh & 7;
    const size_t base = (size_t)(b*2048 + q0 + row2) * 536 + h*67;
    float av_[16] = {acc0.x,acc0.y,acc0.z,acc0.w, acc1.x,acc1.y,acc1.z,acc1.w,
                     acc2.x,acc2.y,acc2.z,acc2.w, acc3.x,acc3.y,acc3.z,acc3.w};
    float* orow = out1 + base + g*16;
#pragma unroll
    for (int q = 0; q < 16; q++) orow[q] = av_[q] * inv;
    if (g < 3) out1[base + 64 + g] = accE * inv;
}

// ======================================================================
extern "C" void kernel_launch(void* const* d_in, const int* in_sizes, int n_in,
                              void* d_out, int out_size)
{
    (void)in_sizes; (void)n_in; (void)out_size;
    const float* x  = (const float*)d_in[0];
    const float* Wq = (const float*)d_in[1];
    const float* Wk = (const float*)d_in[2];
    const float* Wv = (const float*)d_in[3];
    float* out = (float*)d_out;

    cudaFuncSetAttribute(qkv_mma_kernel, cudaFuncAttributeMaxDynamicSharedMemorySize,
                         QKV_SMEM);
    qkv_mma_kernel<<<dim3(8, 64, 3), 256, QKV_SMEM>>>(x, Wq, Wk, Wv);

    dwt_kernel<<<NBH * SEQ, 128>>>(out + OUT1_ELEMS);

    cudaFuncSetAttribute(flash_kernel, cudaFuncAttributeMaxDynamicSharedMemorySize,
                         101120);
    flash_kernel<<<dim3(32, 32), 256, 101120>>>(out);
}

// round 4
// speedup vs baseline: 2.5291x; 2.0535x over previous
#include <cuda_runtime.h>
#include <math.h>
#include <cstdint>

// Problem constants: B=4, S=2048, Hd=1024, H=8, dk=128, wA=67
#define NBH   32           // B*H
#define SEQ   2048
#define DKD   128
#define WAW   67
#define OUT1_ELEMS (4*2048*536)   // B*S*(H*wA)

// ---------------- scratch (static device globals; no allocation) ----------------
__device__ float g_Q[NBH*SEQ*DKD];   // (b,h,s,d), pre-scaled by dk^-0.5
__device__ float g_K[NBH*SEQ*DKD];
__device__ float g_V[NBH*SEQ*DKD];
__device__ float g_cD[NBH*SEQ*WAW];  // (b,h,s,w)

__constant__ float c_lo[8] = { -0.010597401784997278f, 0.032883011666982945f,
                                0.030841381835986965f, -0.18703481171888114f,
                               -0.02798376941698385f,  0.6308807679295904f,
                                0.7148465705525415f,   0.23037781330885523f };
__constant__ float c_hi[8] = { -0.23037781330885523f,  0.7148465705525415f,
                               -0.6308807679295904f,  -0.02798376941698385f,
                                0.18703481171888114f,  0.030841381835986965f,
                               -0.032883011666982945f, -0.010597401784997278f };

__device__ __forceinline__ uint32_t f2tf32(float f) {
    uint32_t u;
    asm("cvt.rna.tf32.f32 %0, %1;" : "=r"(u) : "f"(f));
    return u;
}
__device__ __forceinline__ void split3(float v, uint32_t& big, uint32_t& res) {
    big = f2tf32(v);
    res = f2tf32(v - __uint_as_float(big));
}

__device__ __forceinline__ void mma_tf32(float& d0, float& d1, float& d2, float& d3,
                                         uint32_t a0, uint32_t a1, uint32_t a2, uint32_t a3,
                                         uint32_t b0, uint32_t b1) {
    asm volatile(
        "mma.sync.aligned.m16n8k8.row.col.f32.tf32.tf32.f32 "
        "{%0,%1,%2,%3}, {%4,%5,%6,%7}, {%8,%9}, {%0,%1,%2,%3};"
        : "+f"(d0), "+f"(d1), "+f"(d2), "+f"(d3)
        : "r"(a0), "r"(a1), "r"(a2), "r"(a3), "r"(b0), "r"(b1));
}

// ======================================================================
// Kernel 1: QKV projection via mma.sync tf32 (unchanged from R3 pass).
// ======================================================================
#define CHN 4608            // 128*36 floats per buffer
#define QKV_SMEM (4*CHN*4)  // As[2] + Bs[2] = 73728 bytes

__global__ __launch_bounds__(256) void qkv_mma_kernel(
    const float* __restrict__ x, const float* __restrict__ Wq,
    const float* __restrict__ Wk, const float* __restrict__ Wv)
{
    extern __shared__ float sm[];
    float* As = sm;             // [2][128][36]
    float* Bs = sm + 2*CHN;     // [2][128][36]

    const int tid  = threadIdx.x;
    const int lane = tid & 31;
    const int warp = tid >> 5;
    const int g    = lane >> 2;
    const int tig  = lane & 3;
    const int wm   = warp & 3;
    const int wn   = warp >> 2;

    const int which = blockIdx.z;
    const float* W = (which == 0) ? Wq : ((which == 1) ? Wk : Wv);
    float* O       = (which == 0) ? g_Q : ((which == 1) ? g_K : g_V);
    const float scale = (which == 0) ? 0.08838834764831845f : 1.0f;

    const int m0   = blockIdx.y * 128;
    const int head = blockIdx.x;
    const float* xb = x + (size_t)m0 * 1024;
    const float* wb = W + (size_t)head * 128 * 1024;

    const int lr = tid >> 3;
    const int lc = (tid & 7) * 4;

    float c[2][8][4];
#pragma unroll
    for (int mt = 0; mt < 2; mt++)
#pragma unroll
        for (int nt = 0; nt < 8; nt++)
#pragma unroll
            for (int q = 0; q < 4; q++) c[mt][nt][q] = 0.0f;

    {
#pragma unroll
        for (int u = 0; u < 4; u++) {
            const int r = lr + 32*u;
            const float4 a4 = *(const float4*)(xb + (size_t)r*1024 + lc);
            const float4 b4 = *(const float4*)(wb + (size_t)r*1024 + lc);
            float* pa = As + r*36 + lc;
            float* pb = Bs + r*36 + lc;
            pa[0] = __uint_as_float(f2tf32(a4.x)); pa[1] = __uint_as_float(f2tf32(a4.y));
            pa[2] = __uint_as_float(f2tf32(a4.z)); pa[3] = __uint_as_float(f2tf32(a4.w));
            pb[0] = __uint_as_float(f2tf32(b4.x)); pb[1] = __uint_as_float(f2tf32(b4.y));
            pb[2] = __uint_as_float(f2tf32(b4.z)); pb[3] = __uint_as_float(f2tf32(b4.w));
        }
    }
    __syncthreads();

    for (int ch = 0; ch < 32; ch++) {
        const int cur = ch & 1;
        float4 pfa[4], pfb[4];
        if (ch < 31) {
            const int kb = (ch + 1) << 5;
#pragma unroll
            for (int u = 0; u < 4; u++) {
                const int r = lr + 32*u;
                pfa[u] = *(const float4*)(xb + (size_t)r*1024 + kb + lc);
                pfb[u] = *(const float4*)(wb + (size_t)r*1024 + kb + lc);
            }
        }

        const float* as = As + cur*CHN;
        const float* bs = Bs + cur*CHN;
#pragma unroll
        for (int ks = 0; ks < 4; ks++) {
            const int k0 = ks * 8;
            uint32_t a[2][4];
#pragma unroll
            for (int mt = 0; mt < 2; mt++) {
                const int rb = wm*32 + mt*16 + g;
                a[mt][0] = __float_as_uint(as[(rb    )*36 + k0 + tig]);
                a[mt][1] = __float_as_uint(as[(rb + 8)*36 + k0 + tig]);
                a[mt][2] = __float_as_uint(as[(rb    )*36 + k0 + tig + 4]);
                a[mt][3] = __float_as_uint(as[(rb + 8)*36 + k0 + tig + 4]);
            }
#pragma unroll
            for (int nt = 0; nt < 8; nt++) {
                const int nb = wn*64 + nt*8 + g;
                const uint32_t b0 = __float_as_uint(bs[nb*36 + k0 + tig]);
                const uint32_t b1 = __float_as_uint(bs[nb*36 + k0 + tig + 4]);
#pragma unroll
                for (int mt = 0; mt < 2; mt++)
                    mma_tf32(c[mt][nt][0], c[mt][nt][1], c[mt][nt][2], c[mt][nt][3],
                             a[mt][0], a[mt][1], a[mt][2], a[mt][3], b0, b1);
            }
        }

        if (ch < 31) {
            float* pa0 = As + (cur^1)*CHN;
            float* pb0 = Bs + (cur^1)*CHN;
#pragma unroll
            for (int u = 0; u < 4; u++) {
                const int r = lr + 32*u;
                float* pa = pa0 + r*36 + lc;
                float* pb = pb0 + r*36 + lc;
                pa[0] = __uint_as_float(f2tf32(pfa[u].x)); pa[1] = __uint_as_float(f2tf32(pfa[u].y));
                pa[2] = __uint_as_float(f2tf32(pfa[u].z)); pa[3] = __uint_as_float(f2tf32(pfa[u].w));
                pb[0] = __uint_as_float(f2tf32(pfb[u].x)); pb[1] = __uint_as_float(f2tf32(pfb[u].y));
                pb[2] = __uint_as_float(f2tf32(pfb[u].z)); pb[3] = __uint_as_float(f2tf32(pfb[u].w));
            }
        }
        __syncthreads();
    }

#pragma unroll
    for (int mt = 0; mt < 2; mt++) {
        const int m  = m0 + wm*32 + mt*16 + g;
        const int b0_ = m >> 11, sq = m & 2047;
        float* dst0 = O + (((size_t)(b0_*8 + head) * 2048 + sq) << 7);
        float* dst1 = dst0 + (8 << 7);
#pragma unroll
        for (int nt = 0; nt < 8; nt++) {
            const int d = wn*64 + nt*8 + 2*tig;
            float2 v0 = make_float2(c[mt][nt][0]*scale, c[mt][nt][1]*scale);
            float2 v1 = make_float2(c[mt][nt][2]*scale, c[mt][nt][3]*scale);
            *(float2*)(dst0 + d) = v0;
            *(float2*)(dst1 + d) = v1;
        }
    }
}

// ======================================================================
// Kernel 2: db4 DWT along dk=128 (unchanged).
// ======================================================================
__global__ __launch_bounds__(128) void dwt_kernel(float* __restrict__ out2)
{
    const int rowid = blockIdx.x;
    __shared__ float v[DKD];
    const int t = threadIdx.x;
    v[t] = g_V[(size_t)rowid * DKD + t];
    __syncthreads();
    if (t < WAW) {
        float a = 0.0f, d = 0.0f;
#pragma unroll
        for (int k = 0; k < 8; k++) {
            const int j = 2*t + k;
            const int src = (j < 6) ? (5 - j) : ((j < 134) ? (j - 6) : (261 - j));
            const float e = v[src];
            a = fmaf(e, c_lo[7 - k], a);
            d = fmaf(e, c_hi[7 - k], d);
        }
        out2[(size_t)rowid * WAW + t] = a;
        g_cD[(size_t)rowid * WAW + t] = d;
    }
}

// ======================================================================
// Kernel 3: flash attention fused with (attn @ cD), mma.sync 3xTF32.
// CTA: 128 queries x one bh, 16 key-tiles of 128, online softmax.
// Qs/Ks fp32 stride-132 SMEM; Ps aliases Ks (phase-separated); cDs 128x72.
// S-phase: 8 warps 4Mx2N (warp 32x64). PV: 8 warps x m16 rows x 9 nfrags.
// ======================================================================
#define QS_F   16896      // 128*132
#define CDS_F  9216       // 128*72
#define FL_SMEM ((QS_F*2 + CDS_F + 256 + 256 + 384) * 4)   // 175616 B

__global__ __launch_bounds__(256, 1) void flash_mma_kernel(float* __restrict__ out1)
{
    extern __shared__ float sm[];
    float* Qs   = sm;                    // [128][132] fp32
    float* Ks   = sm + QS_F;             // [128][132] fp32 (aliased as Ps)
    float* Ps   = Ks;
    float* cDs  = sm + 2*QS_F;           // [128][72]
    float* rmax = sm + 2*QS_F + CDS_F;   // [128][2]
    float* rsum = rmax + 256;            // [128][2]
    float* m_s  = rsum + 256;            // [128]
    float* l_s  = m_s + 128;             // [128]
    float* al_s = l_s + 128;             // [128]

    const int tid  = threadIdx.x;
    const int lane = tid & 31;
    const int warp = tid >> 5;
    const int g    = lane >> 2;
    const int tig  = lane & 3;
    const int wm   = warp & 3;
    const int wn   = warp >> 2;

    const int bh = blockIdx.y;
    const int q0 = blockIdx.x * 128;
    const float* Qg  = g_Q  + (size_t)bh * SEQ * DKD;
    const float* Kg  = g_K  + (size_t)bh * SEQ * DKD;
    const float* cDg = g_cD + (size_t)bh * SEQ * WAW;

    // load Q tile (128 x 128) fp32, stride 132
#pragma unroll
    for (int u = 0; u < 16; u++) {
        const int idx = tid + 256*u;
        const int r = idx >> 5, c4 = idx & 31;
        const float4 q4 = *(const float4*)(Qg + (size_t)(q0 + r)*DKD + c4*4);
        *(float4*)(Qs + r*132 + c4*4) = q4;
    }
    if (tid < 128) { m_s[tid] = -1e30f; l_s[tid] = 0.0f; }

    float o[9][4];
#pragma unroll
    for (int nt = 0; nt < 9; nt++)
#pragma unroll
        for (int q = 0; q < 4; q++) o[nt][q] = 0.0f;

    __syncthreads();

    for (int kt = 0; kt < 16; kt++) {
        const int n0 = kt * 128;
        // ---- load K tile + cD tile ----
#pragma unroll
        for (int u = 0; u < 16; u++) {
            const int idx = tid + 256*u;
            const int r = idx >> 5, c4 = idx & 31;
            const float4 k4 = *(const float4*)(Kg + (size_t)(n0 + r)*DKD + c4*4);
            *(float4*)(Ks + r*132 + c4*4) = k4;
        }
#pragma unroll
        for (int u = 0; u < 36; u++) {
            const int idx = tid + 256*u;
            const int r = idx / 72, w = idx - r*72;
            cDs[idx] = (w < WAW) ? cDg[(size_t)(n0 + r)*WAW + w] : 0.0f;
        }
        __syncthreads();

        // ---- S = Q K^T, 3xTF32 ----
        float s[2][8][4];
#pragma unroll
        for (int mt = 0; mt < 2; mt++)
#pragma unroll
            for (int nt = 0; nt < 8; nt++)
#pragma unroll
                for (int q = 0; q < 4; q++) s[mt][nt][q] = 0.0f;

#pragma unroll 4
        for (int ks = 0; ks < 16; ks++) {
            const int k0 = ks * 8;
            uint32_t ab[2][4], ar[2][4];
#pragma unroll
            for (int mt = 0; mt < 2; mt++) {
                const int rb = wm*32 + mt*16 + g;
                split3(Qs[(rb    )*132 + k0 + tig],     ab[mt][0], ar[mt][0]);
                split3(Qs[(rb + 8)*132 + k0 + tig],     ab[mt][1], ar[mt][1]);
                split3(Qs[(rb    )*132 + k0 + tig + 4], ab[mt][2], ar[mt][2]);
                split3(Qs[(rb + 8)*132 + k0 + tig + 4], ab[mt][3], ar[mt][3]);
            }
#pragma unroll
            for (int nt = 0; nt < 8; nt++) {
                const int nb = wn*64 + nt*8 + g;
                uint32_t bb0, br0, bb1, br1;
                split3(Ks[nb*132 + k0 + tig],     bb0, br0);
                split3(Ks[nb*132 + k0 + tig + 4], bb1, br1);
#pragma unroll
                for (int mt = 0; mt < 2; mt++) {
                    mma_tf32(s[mt][nt][0], s[mt][nt][1], s[mt][nt][2], s[mt][nt][3],
                             ab[mt][0], ab[mt][1], ab[mt][2], ab[mt][3], bb0, bb1);
                    mma_tf32(s[mt][nt][0], s[mt][nt][1], s[mt][nt][2], s[mt][nt][3],
                             ab[mt][0], ab[mt][1], ab[mt][2], ab[mt][3], br0, br1);
                    mma_tf32(s[mt][nt][0], s[mt][nt][1], s[mt][nt][2], s[mt][nt][3],
                             ar[mt][0], ar[mt][1], ar[mt][2], ar[mt][3], bb0, bb1);
                }
            }
        }

        // ---- row max (warp shfl over quad, then cross-warp via SMEM) ----
        float mx[2][2];
#pragma unroll
        for (int mt = 0; mt < 2; mt++)
#pragma unroll
            for (int hf = 0; hf < 2; hf++) {
                float m = -1e30f;
#pragma unroll
                for (int nt = 0; nt < 8; nt++)
                    m = fmaxf(m, fmaxf(s[mt][nt][2*hf], s[mt][nt][2*hf+1]));
                m = fmaxf(m, __shfl_xor_sync(0xffffffffu, m, 1));
                m = fmaxf(m, __shfl_xor_sync(0xffffffffu, m, 2));
                mx[mt][hf] = m;
            }
        if (tig == 0) {
#pragma unroll
            for (int mt = 0; mt < 2; mt++)
#pragma unroll
                for (int hf = 0; hf < 2; hf++) {
                    const int row = wm*32 + mt*16 + g + 8*hf;
                    rmax[row*2 + wn] = mx[mt][hf];
                }
        }
        __syncthreads();   // also: all Ks reads complete -> Ps writes legal

        float mnew[2][2], alv[2][2], ssum[2][2];
#pragma unroll
        for (int mt = 0; mt < 2; mt++)
#pragma unroll
            for (int hf = 0; hf < 2; hf++) {
                const int row = wm*32 + mt*16 + g + 8*hf;
                const float tm = fmaxf(rmax[row*2], rmax[row*2+1]);
                const float mo = m_s[row];
                const float mn = fmaxf(mo, tm);
                mnew[mt][hf] = mn;
                alv[mt][hf]  = __expf(mo - mn);
                ssum[mt][hf] = 0.0f;
            }
#pragma unroll
        for (int mt = 0; mt < 2; mt++) {
            const int r0 = wm*32 + mt*16 + g;
#pragma unroll
            for (int nt = 0; nt < 8; nt++) {
                const int col = wn*64 + nt*8 + 2*tig;
                float p0 = __expf(s[mt][nt][0] - mnew[mt][0]);
                float p1 = __expf(s[mt][nt][1] - mnew[mt][0]);
                float p2 = __expf(s[mt][nt][2] - mnew[mt][1]);
                float p3 = __expf(s[mt][nt][3] - mnew[mt][1]);
                ssum[mt][0] += p0 + p1;
                ssum[mt][1] += p2 + p3;
                *(float2*)(Ps + (r0    )*132 + col) = make_float2(p0, p1);
                *(float2*)(Ps + (r0 + 8)*132 + col) = make_float2(p2, p3);
            }
        }
#pragma unroll
        for (int mt = 0; mt < 2; mt++)
#pragma unroll
            for (int hf = 0; hf < 2; hf++) {
                float sv = ssum[mt][hf];
                sv += __shfl_xor_sync(0xffffffffu, sv, 1);
                sv += __shfl_xor_sync(0xffffffffu, sv, 2);
                if (tig == 0) {
                    const int row = wm*32 + mt*16 + g + 8*hf;
                    rsum[row*2 + wn] = sv;
                }
            }
        __syncthreads();

        if (wn == 0 && tig == 0) {
#pragma unroll
            for (int mt = 0; mt < 2; mt++)
#pragma unroll
                for (int hf = 0; hf < 2; hf++) {
                    const int row = wm*32 + mt*16 + g + 8*hf;
                    const float ts = rsum[row*2] + rsum[row*2+1];
                    l_s[row]  = l_s[row]*alv[mt][hf] + ts;
                    m_s[row]  = mnew[mt][hf];
                    al_s[row] = alv[mt][hf];
                }
        }
        __syncthreads();

        // ---- PV: o += P @ cD (3xTF32), rows warp*16..+16, 9 n-frags ----
        {
            const int rb = warp*16 + g;
            const float a0 = al_s[rb], a1 = al_s[rb + 8];
#pragma unroll
            for (int nt = 0; nt < 9; nt++) {
                o[nt][0] *= a0; o[nt][1] *= a0;
                o[nt][2] *= a1; o[nt][3] *= a1;
            }
#pragma unroll 4
            for (int ks = 0; ks < 16; ks++) {
                const int k0 = ks * 8;
                uint32_t pb[4], pr[4];
                split3(Ps[(rb    )*132 + k0 + tig],     pb[0], pr[0]);
                split3(Ps[(rb + 8)*132 + k0 + tig],     pb[1], pr[1]);
                split3(Ps[(rb    )*132 + k0 + tig + 4], pb[2], pr[2]);
                split3(Ps[(rb + 8)*132 + k0 + tig + 4], pb[3], pr[3]);
#pragma unroll
                for (int nt = 0; nt < 9; nt++) {
                    uint32_t cb0, cr0, cb1, cr1;
                    split3(cDs[(k0 + tig    )*72 + nt*8 + g], cb0, cr0);
                    split3(cDs[(k0 + tig + 4)*72 + nt*8 + g], cb1, cr1);
                    mma_tf32(o[nt][0], o[nt][1], o[nt][2], o[nt][3],
                             pb[0], pb[1], pb[2], pb[3], cb0, cb1);
                    mma_tf32(o[nt][0], o[nt][1], o[nt][2], o[nt][3],
                             pb[0], pb[1], pb[2], pb[3], cr0, cr1);
                    mma_tf32(o[nt][0], o[nt][1], o[nt][2], o[nt][3],
                             pr[0], pr[1], pr[2], pr[3], cb0, cb1);
                }
            }
        }
        __syncthreads();   // before next tile overwrites Ks(=Ps)/cDs
    }

    // ---- epilogue ----
    const int rb = warp*16 + g;
    const float inv0 = 1.0f / l_s[rb];
    const float inv1 = 1.0f / l_s[rb + 8];
    const int b = bh >> 3, h = bh & 7;
    const size_t base0 = (size_t)(b*2048 + q0 + rb) * 536 + h*67;
    const size_t base1 = base0 + (size_t)8 * 536;
#pragma unroll
    for (int nt = 0; nt < 9; nt++) {
        const int col = nt*8 + 2*tig;
        if (col < WAW) {
            out1[base0 + col] = o[nt][0] * inv0;
            out1[base1 + col] = o[nt][2] * inv1;
        }
        if (col + 1 < WAW) {
            out1[base0 + col + 1] = o[nt][1] * inv0;
            out1[base1 + col + 1] = o[nt][3] * inv1;
        }
    }
}

// ======================================================================
extern "C" void kernel_launch(void* const* d_in, const int* in_sizes, int n_in,
                              void* d_out, int out_size)
{
    (void)in_sizes; (void)n_in; (void)out_size;
    const float* x  = (const float*)d_in[0];
    const float* Wq = (const float*)d_in[1];
    const float* Wk = (const float*)d_in[2];
    const float* Wv = (const float*)d_in[3];
    float* out = (float*)d_out;

    cudaFuncSetAttribute(qkv_mma_kernel, cudaFuncAttributeMaxDynamicSharedMemorySize,
                         QKV_SMEM);
    qkv_mma_kernel<<<dim3(8, 64, 3), 256, QKV_SMEM>>>(x, Wq, Wk, Wv);

    dwt_kernel<<<NBH * SEQ, 128>>>(out + OUT1_ELEMS);

    cudaFuncSetAttribute(flash_mma_kernel, cudaFuncAttributeMaxDynamicSharedMemorySize,
                         FL_SMEM);
    flash_mma_kernel<<<dim3(16, 32), 256, FL_SMEM>>>(out);
}

// round 5
// speedup vs baseline: 4.3238x; 1.7096x over previous
#include <cuda_runtime.h>
#include <cuda_fp16.h>
#include <math.h>
#include <cstdint>

// Problem constants: B=4, S=2048, Hd=1024, H=8, dk=128, wA=67
#define NBH   32           // B*H
#define SEQ   2048
#define DKD   128
#define WAW   67
#define OUT1_ELEMS (4*2048*536)   // B*S*(H*wA)

// ---------------- scratch (static device globals; no allocation) ----------------
__device__ float g_Q[NBH*SEQ*DKD];   // (b,h,s,d), pre-scaled by dk^-0.5
__device__ float g_K[NBH*SEQ*DKD];
__device__ float g_V[NBH*SEQ*DKD];
__device__ float g_cD[NBH*SEQ*WAW];  // (b,h,s,w)

__constant__ float c_lo[8] = { -0.010597401784997278f, 0.032883011666982945f,
                                0.030841381835986965f, -0.18703481171888114f,
                               -0.02798376941698385f,  0.6308807679295904f,
                                0.7148465705525415f,   0.23037781330885523f };
__constant__ float c_hi[8] = { -0.23037781330885523f,  0.7148465705525415f,
                               -0.6308807679295904f,  -0.02798376941698385f,
                                0.18703481171888114f,  0.030841381835986965f,
                               -0.032883011666982945f, -0.010597401784997278f };

__device__ __forceinline__ uint32_t f2tf32(float f) {
    uint32_t u;
    asm("cvt.rna.tf32.f32 %0, %1;" : "=r"(u) : "f"(f));
    return u;
}

__device__ __forceinline__ void mma_tf32(float& d0, float& d1, float& d2, float& d3,
                                         uint32_t a0, uint32_t a1, uint32_t a2, uint32_t a3,
                                         uint32_t b0, uint32_t b1) {
    asm volatile(
        "mma.sync.aligned.m16n8k8.row.col.f32.tf32.tf32.f32 "
        "{%0,%1,%2,%3}, {%4,%5,%6,%7}, {%8,%9}, {%0,%1,%2,%3};"
        : "+f"(d0), "+f"(d1), "+f"(d2), "+f"(d3)
        : "r"(a0), "r"(a1), "r"(a2), "r"(a3), "r"(b0), "r"(b1));
}

__device__ __forceinline__ void mma_f16(float& d0, float& d1, float& d2, float& d3,
                                        uint32_t a0, uint32_t a1, uint32_t a2, uint32_t a3,
                                        uint32_t b0, uint32_t b1) {
    asm volatile(
        "mma.sync.aligned.m16n8k16.row.col.f32.f16.f16.f32 "
        "{%0,%1,%2,%3}, {%4,%5,%6,%7}, {%8,%9}, {%0,%1,%2,%3};"
        : "+f"(d0), "+f"(d1), "+f"(d2), "+f"(d3)
        : "r"(a0), "r"(a1), "r"(a2), "r"(a3), "r"(b0), "r"(b1));
}

// split fp32 pair -> fp16 hi pair + fp16 lo (residual) pair, packed as b32
__device__ __forceinline__ void split_h2(float x, float y, uint32_t& hi, uint32_t& lo) {
    __half2 h = __float22half2_rn(make_float2(x, y));
    float2 b = __half22float2(h);
    __half2 l = __float22half2_rn(make_float2(x - b.x, y - b.y));
    hi = *(uint32_t*)&h;
    lo = *(uint32_t*)&l;
}

// ======================================================================
// Kernel 1: QKV projection via mma.sync tf32 (unchanged from R3/R4 pass).
// ======================================================================
#define CHN 4608            // 128*36 floats per buffer
#define QKV_SMEM (4*CHN*4)  // As[2] + Bs[2] = 73728 bytes

__global__ __launch_bounds__(256) void qkv_mma_kernel(
    const float* __restrict__ x, const float* __restrict__ Wq,
    const float* __restrict__ Wk, const float* __restrict__ Wv)
{
    extern __shared__ float sm[];
    float* As = sm;             // [2][128][36]
    float* Bs = sm + 2*CHN;     // [2][128][36]

    const int tid  = threadIdx.x;
    const int lane = tid & 31;
    const int warp = tid >> 5;
    const int g    = lane >> 2;
    const int tig  = lane & 3;
    const int wm   = warp & 3;
    const int wn   = warp >> 2;

    const int which = blockIdx.z;
    const float* W = (which == 0) ? Wq : ((which == 1) ? Wk : Wv);
    float* O       = (which == 0) ? g_Q : ((which == 1) ? g_K : g_V);
    const float scale = (which == 0) ? 0.08838834764831845f : 1.0f;

    const int m0   = blockIdx.y * 128;
    const int head = blockIdx.x;
    const float* xb = x + (size_t)m0 * 1024;
    const float* wb = W + (size_t)head * 128 * 1024;

    const int lr = tid >> 3;
    const int lc = (tid & 7) * 4;

    float c[2][8][4];
#pragma unroll
    for (int mt = 0; mt < 2; mt++)
#pragma unroll
        for (int nt = 0; nt < 8; nt++)
#pragma unroll
            for (int q = 0; q < 4; q++) c[mt][nt][q] = 0.0f;

    {
#pragma unroll
        for (int u = 0; u < 4; u++) {
            const int r = lr + 32*u;
            const float4 a4 = *(const float4*)(xb + (size_t)r*1024 + lc);
            const float4 b4 = *(const float4*)(wb + (size_t)r*1024 + lc);
            float* pa = As + r*36 + lc;
            float* pb = Bs + r*36 + lc;
            pa[0] = __uint_as_float(f2tf32(a4.x)); pa[1] = __uint_as_float(f2tf32(a4.y));
            pa[2] = __uint_as_float(f2tf32(a4.z)); pa[3] = __uint_as_float(f2tf32(a4.w));
            pb[0] = __uint_as_float(f2tf32(b4.x)); pb[1] = __uint_as_float(f2tf32(b4.y));
            pb[2] = __uint_as_float(f2tf32(b4.z)); pb[3] = __uint_as_float(f2tf32(b4.w));
        }
    }
    __syncthreads();

    for (int ch = 0; ch < 32; ch++) {
        const int cur = ch & 1;
        float4 pfa[4], pfb[4];
        if (ch < 31) {
            const int kb = (ch + 1) << 5;
#pragma unroll
            for (int u = 0; u < 4; u++) {
                const int r = lr + 32*u;
                pfa[u] = *(const float4*)(xb + (size_t)r*1024 + kb + lc);
                pfb[u] = *(const float4*)(wb + (size_t)r*1024 + kb + lc);
            }
        }

        const float* as = As + cur*CHN;
        const float* bs = Bs + cur*CHN;
#pragma unroll
        for (int ks = 0; ks < 4; ks++) {
            const int k0 = ks * 8;
            uint32_t a[2][4];
#pragma unroll
            for (int mt = 0; mt < 2; mt++) {
                const int rb = wm*32 + mt*16 + g;
                a[mt][0] = __float_as_uint(as[(rb    )*36 + k0 + tig]);
                a[mt][1] = __float_as_uint(as[(rb + 8)*36 + k0 + tig]);
                a[mt][2] = __float_as_uint(as[(rb    )*36 + k0 + tig + 4]);
                a[mt][3] = __float_as_uint(as[(rb + 8)*36 + k0 + tig + 4]);
            }
#pragma unroll
            for (int nt = 0; nt < 8; nt++) {
                const int nb = wn*64 + nt*8 + g;
                const uint32_t b0 = __float_as_uint(bs[nb*36 + k0 + tig]);
                const uint32_t b1 = __float_as_uint(bs[nb*36 + k0 + tig + 4]);
#pragma unroll
                for (int mt = 0; mt < 2; mt++)
                    mma_tf32(c[mt][nt][0], c[mt][nt][1], c[mt][nt][2], c[mt][nt][3],
                             a[mt][0], a[mt][1], a[mt][2], a[mt][3], b0, b1);
            }
        }

        if (ch < 31) {
            float* pa0 = As + (cur^1)*CHN;
            float* pb0 = Bs + (cur^1)*CHN;
#pragma unroll
            for (int u = 0; u < 4; u++) {
                const int r = lr + 32*u;
                float* pa = pa0 + r*36 + lc;
                float* pb = pb0 + r*36 + lc;
                pa[0] = __uint_as_float(f2tf32(pfa[u].x)); pa[1] = __uint_as_float(f2tf32(pfa[u].y));
                pa[2] = __uint_as_float(f2tf32(pfa[u].z)); pa[3] = __uint_as_float(f2tf32(pfa[u].w));
                pb[0] = __uint_as_float(f2tf32(pfb[u].x)); pb[1] = __uint_as_float(f2tf32(pfb[u].y));
                pb[2] = __uint_as_float(f2tf32(pfb[u].z)); pb[3] = __uint_as_float(f2tf32(pfb[u].w));
            }
        }
        __syncthreads();
    }

#pragma unroll
    for (int mt = 0; mt < 2; mt++) {
        const int m  = m0 + wm*32 + mt*16 + g;
        const int b0_ = m >> 11, sq = m & 2047;
        float* dst0 = O + (((size_t)(b0_*8 + head) * 2048 + sq) << 7);
        float* dst1 = dst0 + (8 << 7);
#pragma unroll
        for (int nt = 0; nt < 8; nt++) {
            const int d = wn*64 + nt*8 + 2*tig;
            float2 v0 = make_float2(c[mt][nt][0]*scale, c[mt][nt][1]*scale);
            float2 v1 = make_float2(c[mt][nt][2]*scale, c[mt][nt][3]*scale);
            *(float2*)(dst0 + d) = v0;
            *(float2*)(dst1 + d) = v1;
        }
    }
}

// ======================================================================
// Kernel 2: db4 DWT along dk=128 (unchanged).
// ======================================================================
__global__ __launch_bounds__(128) void dwt_kernel(float* __restrict__ out2)
{
    const int rowid = blockIdx.x;
    __shared__ float v[DKD];
    const int t = threadIdx.x;
    v[t] = g_V[(size_t)rowid * DKD + t];
    __syncthreads();
    if (t < WAW) {
        float a = 0.0f, d = 0.0f;
#pragma unroll
        for (int k = 0; k < 8; k++) {
            const int j = 2*t + k;
            const int src = (j < 6) ? (5 - j) : ((j < 134) ? (j - 6) : (261 - j));
            const float e = v[src];
            a = fmaf(e, c_lo[7 - k], a);
            d = fmaf(e, c_hi[7 - k], d);
        }
        out2[(size_t)rowid * WAW + t] = a;
        g_cD[(size_t)rowid * WAW + t] = d;
    }
}

// ======================================================================
// Kernel 3: flash attention fused with (attn @ cD).
// fp16 hi/lo split (Markidis, 3 MMAs m16n8k16) == fp32-grade accuracy.
// Splits PRECOMPUTED into SMEM: Q once/CTA, K/cD once/tile, P at write.
// All tiles stride 68 b32 (== 4 mod 32) -> conflict-free fragment LDS.
// Phi/Plo alias Khi/Klo (phase-separated). cD stored transposed [w][key].
// ======================================================================
#define SH68   68                 // b32 stride per row
#define QT_B32 (128*SH68)         // 8704 b32 per 128-row tile
#define FL_SMEM ((4*QT_B32 + 2*72*SH68 + 896) * 4)   // 182016 B

__global__ __launch_bounds__(256, 1) void flash_f16_kernel(float* __restrict__ out1)
{
    extern __shared__ __align__(16) uint32_t smw[];
    uint32_t* Qhi  = smw;                   // [128][68]
    uint32_t* Qlo  = Qhi + QT_B32;
    uint32_t* Khi  = Qlo + QT_B32;          // aliased as Phi
    uint32_t* Klo  = Khi + QT_B32;          // aliased as Plo
    uint32_t* cDhi = Klo + QT_B32;          // [72][68]  (transposed: [w][key])
    uint32_t* cDlo = cDhi + 72*SH68;
    float* rmax = (float*)(cDlo + 72*SH68); // [128][2]
    float* rsum = rmax + 256;               // [128][2]
    float* m_s  = rsum + 256;               // [128]
    float* l_s  = m_s + 128;                // [128]
    float* al_s = l_s + 128;                // [128]

    const int tid  = threadIdx.x;
    const int lane = tid & 31;
    const int warp = tid >> 5;
    const int g    = lane >> 2;
    const int tig  = lane & 3;
    const int wm   = warp & 3;
    const int wn   = warp >> 2;

    const int bh = blockIdx.y;
    const int q0 = blockIdx.x * 128;
    const float* Qg  = g_Q  + (size_t)bh * SEQ * DKD;
    const float* Kg  = g_K  + (size_t)bh * SEQ * DKD;
    const float* cDg = g_cD + (size_t)bh * SEQ * WAW;

    // ---- load + split Q (once) ----
#pragma unroll
    for (int u = 0; u < 16; u++) {
        const int idx = tid + 256*u;
        const int r = idx >> 5, c4 = idx & 31;
        const float4 q4 = *(const float4*)(Qg + (size_t)(q0 + r)*DKD + c4*4);
        uint32_t h0, l0, h1, l1;
        split_h2(q4.x, q4.y, h0, l0);
        split_h2(q4.z, q4.w, h1, l1);
        Qhi[r*SH68 + 2*c4]     = h0;  Qhi[r*SH68 + 2*c4 + 1] = h1;
        Qlo[r*SH68 + 2*c4]     = l0;  Qlo[r*SH68 + 2*c4 + 1] = l1;
    }
    // zero cD pad rows 67..71 (written never, read by nt=8 frags)
    for (int i = tid; i < 5*SH68; i += 256) {
        cDhi[67*SH68 + i] = 0;
        cDlo[67*SH68 + i] = 0;
    }
    if (tid < 128) { m_s[tid] = -1e30f; l_s[tid] = 0.0f; }

    float o[9][4];
#pragma unroll
    for (int nt = 0; nt < 9; nt++)
#pragma unroll
        for (int q = 0; q < 4; q++) o[nt][q] = 0.0f;

    __syncthreads();

    for (int kt = 0; kt < 16; kt++) {
        const int n0 = kt * 128;
        // ---- load + split K tile ----
#pragma unroll
        for (int u = 0; u < 16; u++) {
            const int idx = tid + 256*u;
            const int r = idx >> 5, c4 = idx & 31;
            const float4 k4 = *(const float4*)(Kg + (size_t)(n0 + r)*DKD + c4*4);
            uint32_t h0, l0, h1, l1;
            split_h2(k4.x, k4.y, h0, l0);
            split_h2(k4.z, k4.w, h1, l1);
            Khi[r*SH68 + 2*c4]     = h0;  Khi[r*SH68 + 2*c4 + 1] = h1;
            Klo[r*SH68 + 2*c4]     = l0;  Klo[r*SH68 + 2*c4 + 1] = l1;
        }
        // ---- load + split cD tile, TRANSPOSED: [w][key], keys packed in pairs ----
#pragma unroll
        for (int u = 0; u < 16; u++) {
            const int idx = tid + 256*u;
            const int j2 = idx >> 6, w = idx & 63;
            const float v0 = cDg[(size_t)(n0 + 2*j2    )*WAW + w];
            const float v1 = cDg[(size_t)(n0 + 2*j2 + 1)*WAW + w];
            uint32_t h, l;
            split_h2(v0, v1, h, l);
            cDhi[w*SH68 + j2] = h;
            cDlo[w*SH68 + j2] = l;
        }
        {   // tail: w = 64..66
            const int wt = tid & 3, j2 = tid >> 2;
            if (wt < 3) {
                const int w = 64 + wt;
                const float v0 = cDg[(size_t)(n0 + 2*j2    )*WAW + w];
                const float v1 = cDg[(size_t)(n0 + 2*j2 + 1)*WAW + w];
                uint32_t h, l;
                split_h2(v0, v1, h, l);
                cDhi[w*SH68 + j2] = h;
                cDlo[w*SH68 + j2] = l;
            }
        }
        __syncthreads();

        // ---- S = Q K^T : fp16 hi/lo, 3 MMAs per fragment ----
        float s[2][8][4];
#pragma unroll
        for (int mt = 0; mt < 2; mt++)
#pragma unroll
            for (int nt = 0; nt < 8; nt++)
#pragma unroll
                for (int q = 0; q < 4; q++) s[mt][nt][q] = 0.0f;

#pragma unroll 2
        for (int ks = 0; ks < 8; ks++) {
            const int k0b = ks * 8;
            uint32_t ah[2][4], al_[2][4];
#pragma unroll
            for (int mt = 0; mt < 2; mt++) {
                const int rb = wm*32 + mt*16 + g;
                ah[mt][0] = Qhi[(rb    )*SH68 + k0b + tig];
                ah[mt][1] = Qhi[(rb + 8)*SH68 + k0b + tig];
                ah[mt][2] = Qhi[(rb    )*SH68 + k0b + tig + 4];
                ah[mt][3] = Qhi[(rb + 8)*SH68 + k0b + tig + 4];
                al_[mt][0] = Qlo[(rb    )*SH68 + k0b + tig];
                al_[mt][1] = Qlo[(rb + 8)*SH68 + k0b + tig];
                al_[mt][2] = Qlo[(rb    )*SH68 + k0b + tig + 4];
                al_[mt][3] = Qlo[(rb + 8)*SH68 + k0b + tig + 4];
            }
#pragma unroll
            for (int nt = 0; nt < 8; nt++) {
                const int nb = wn*64 + nt*8 + g;
                const uint32_t bh0 = Khi[nb*SH68 + k0b + tig];
                const uint32_t bh1 = Khi[nb*SH68 + k0b + tig + 4];
                const uint32_t bl0 = Klo[nb*SH68 + k0b + tig];
                const uint32_t bl1 = Klo[nb*SH68 + k0b + tig + 4];
#pragma unroll
                for (int mt = 0; mt < 2; mt++) {
                    mma_f16(s[mt][nt][0], s[mt][nt][1], s[mt][nt][2], s[mt][nt][3],
                            ah[mt][0], ah[mt][1], ah[mt][2], ah[mt][3], bh0, bh1);
                    mma_f16(s[mt][nt][0], s[mt][nt][1], s[mt][nt][2], s[mt][nt][3],
                            ah[mt][0], ah[mt][1], ah[mt][2], ah[mt][3], bl0, bl1);
                    mma_f16(s[mt][nt][0], s[mt][nt][1], s[mt][nt][2], s[mt][nt][3],
                            al_[mt][0], al_[mt][1], al_[mt][2], al_[mt][3], bh0, bh1);
                }
            }
        }

        // ---- row max (quad shfl + cross-warp SMEM) ----
        float mx[2][2];
#pragma unroll
        for (int mt = 0; mt < 2; mt++)
#pragma unroll
            for (int hf = 0; hf < 2; hf++) {
                float m = -1e30f;
#pragma unroll
                for (int nt = 0; nt < 8; nt++)
                    m = fmaxf(m, fmaxf(s[mt][nt][2*hf], s[mt][nt][2*hf+1]));
                m = fmaxf(m, __shfl_xor_sync(0xffffffffu, m, 1));
                m = fmaxf(m, __shfl_xor_sync(0xffffffffu, m, 2));
                mx[mt][hf] = m;
            }
        if (tig == 0) {
#pragma unroll
            for (int mt = 0; mt < 2; mt++)
#pragma unroll
                for (int hf = 0; hf < 2; hf++) {
                    const int row = wm*32 + mt*16 + g + 8*hf;
                    rmax[row*2 + wn] = mx[mt][hf];
                }
        }
        __syncthreads();   // all K-fragment reads done -> P writes legal

        float mnew[2][2], alv[2][2], ssum[2][2];
#pragma unroll
        for (int mt = 0; mt < 2; mt++)
#pragma unroll
            for (int hf = 0; hf < 2; hf++) {
                const int row = wm*32 + mt*16 + g + 8*hf;
                const float tm = fmaxf(rmax[row*2], rmax[row*2+1]);
                const float mo = m_s[row];
                const float mn = fmaxf(mo, tm);
                mnew[mt][hf] = mn;
                alv[mt][hf]  = __expf(mo - mn);
                ssum[mt][hf] = 0.0f;
            }
#pragma unroll
        for (int mt = 0; mt < 2; mt++) {
            const int r0 = wm*32 + mt*16 + g;
#pragma unroll
            for (int nt = 0; nt < 8; nt++) {
                const int cb = 32*wn + 4*nt + tig;     // b32 col
                float p0 = __expf(s[mt][nt][0] - mnew[mt][0]);
                float p1 = __expf(s[mt][nt][1] - mnew[mt][0]);
                float p2 = __expf(s[mt][nt][2] - mnew[mt][1]);
                float p3 = __expf(s[mt][nt][3] - mnew[mt][1]);
                ssum[mt][0] += p0 + p1;
                ssum[mt][1] += p2 + p3;
                uint32_t h, l;
                split_h2(p0, p1, h, l);
                Khi[(r0    )*SH68 + cb] = h;   // Phi
                Klo[(r0    )*SH68 + cb] = l;   // Plo
                split_h2(p2, p3, h, l);
                Khi[(r0 + 8)*SH68 + cb] = h;
                Klo[(r0 + 8)*SH68 + cb] = l;
            }
        }
#pragma unroll
        for (int mt = 0; mt < 2; mt++)
#pragma unroll
            for (int hf = 0; hf < 2; hf++) {
                float sv = ssum[mt][hf];
                sv += __shfl_xor_sync(0xffffffffu, sv, 1);
                sv += __shfl_xor_sync(0xffffffffu, sv, 2);
                if (tig == 0) {
                    const int row = wm*32 + mt*16 + g + 8*hf;
                    rsum[row*2 + wn] = sv;
                }
            }
        __syncthreads();

        if (wn == 0 && tig == 0) {
#pragma unroll
            for (int mt = 0; mt < 2; mt++)
#pragma unroll
                for (int hf = 0; hf < 2; hf++) {
                    const int row = wm*32 + mt*16 + g + 8*hf;
                    const float ts = rsum[row*2] + rsum[row*2+1];
                    l_s[row]  = l_s[row]*alv[mt][hf] + ts;
                    m_s[row]  = mnew[mt][hf];
                    al_s[row] = alv[mt][hf];
                }
        }
        __syncthreads();

        // ---- PV: o += P @ cD^T, fp16 hi/lo 3-MMA ----
        {
            const int rb = warp*16 + g;
            const float a0 = al_s[rb], a1 = al_s[rb + 8];
#pragma unroll
            for (int nt = 0; nt < 9; nt++) {
                o[nt][0] *= a0; o[nt][1] *= a0;
                o[nt][2] *= a1; o[nt][3] *= a1;
            }
#pragma unroll 2
            for (int ks = 0; ks < 8; ks++) {
                const int k0b = ks * 8;
                uint32_t ph[4], pl[4];
                ph[0] = Khi[(rb    )*SH68 + k0b + tig];
                ph[1] = Khi[(rb + 8)*SH68 + k0b + tig];
                ph[2] = Khi[(rb    )*SH68 + k0b + tig + 4];
                ph[3] = Khi[(rb + 8)*SH68 + k0b + tig + 4];
                pl[0] = Klo[(rb    )*SH68 + k0b + tig];
                pl[1] = Klo[(rb + 8)*SH68 + k0b + tig];
                pl[2] = Klo[(rb    )*SH68 + k0b + tig + 4];
                pl[3] = Klo[(rb + 8)*SH68 + k0b + tig + 4];
#pragma unroll
                for (int nt = 0; nt < 9; nt++) {
                    const int wr = nt*8 + g;
                    const uint32_t ch0 = cDhi[wr*SH68 + k0b + tig];
                    const uint32_t ch1 = cDhi[wr*SH68 + k0b + tig + 4];
                    const uint32_t cl0 = cDlo[wr*SH68 + k0b + tig];
                    const uint32_t cl1 = cDlo[wr*SH68 + k0b + tig + 4];
                    mma_f16(o[nt][0], o[nt][1], o[nt][2], o[nt][3],
                            ph[0], ph[1], ph[2], ph[3], ch0, ch1);
                    mma_f16(o[nt][0], o[nt][1], o[nt][2], o[nt][3],
                            ph[0], ph[1], ph[2], ph[3], cl0, cl1);
                    mma_f16(o[nt][0], o[nt][1], o[nt][2], o[nt][3],
                            pl[0], pl[1], pl[2], pl[3], ch0, ch1);
                }
            }
        }
        __syncthreads();   // before next tile overwrites K(=P)/cD
    }

    // ---- epilogue ----
    const int rb = warp*16 + g;
    const float inv0 = 1.0f / l_s[rb];
    const float inv1 = 1.0f / l_s[rb + 8];
    const int b = bh >> 3, h = bh & 7;
    const size_t base0 = (size_t)(b*2048 + q0 + rb) * 536 + h*67;
    const size_t base1 = base0 + (size_t)8 * 536;
#pragma unroll
    for (int nt = 0; nt < 9; nt++) {
        const int col = nt*8 + 2*tig;
        if (col < WAW) {
            out1[base0 + col] = o[nt][0] * inv0;
            out1[base1 + col] = o[nt][2] * inv1;
        }
        if (col + 1 < WAW) {
            out1[base0 + col + 1] = o[nt][1] * inv0;
            out1[base1 + col + 1] = o[nt][3] * inv1;
        }
    }
}

// ======================================================================
extern "C" void kernel_launch(void* const* d_in, const int* in_sizes, int n_in,
                              void* d_out, int out_size)
{
    (void)in_sizes; (void)n_in; (void)out_size;
    const float* x  = (const float*)d_in[0];
    const float* Wq = (const float*)d_in[1];
    const float* Wk = (const float*)d_in[2];
    const float* Wv = (const float*)d_in[3];
    float* out = (float*)d_out;

    cudaFuncSetAttribute(qkv_mma_kernel, cudaFuncAttributeMaxDynamicSharedMemorySize,
                         QKV_SMEM);
    qkv_mma_kernel<<<dim3(8, 64, 3), 256, QKV_SMEM>>>(x, Wq, Wk, Wv);

    dwt_kernel<<<NBH * SEQ, 128>>>(out + OUT1_ELEMS);

    cudaFuncSetAttribute(flash_f16_kernel, cudaFuncAttributeMaxDynamicSharedMemorySize,
                         FL_SMEM);
    flash_f16_kernel<<<dim3(16, 32), 256, FL_SMEM>>>(out);
}

// round 6
// speedup vs baseline: 4.4315x; 1.0249x over previous
#include <cuda_runtime.h>
#include <cuda_fp16.h>
#include <math.h>
#include <cstdint>

// Problem constants: B=4, S=2048, Hd=1024, H=8, dk=128, wA=67
#define NBH   32           // B*H
#define SEQ   2048
#define DKD   128
#define WAW   67
#define OUT1_ELEMS (4*2048*536)   // B*S*(H*wA)

// ---------------- scratch (static device globals; no allocation) ----------------
__device__ float g_Q[NBH*SEQ*DKD];   // (b,h,s,d), pre-scaled by dk^-0.5
__device__ float g_K[NBH*SEQ*DKD];
__device__ float g_cD[NBH*SEQ*WAW];  // (b,h,s,w)

__constant__ float c_lo[8] = { -0.010597401784997278f, 0.032883011666982945f,
                                0.030841381835986965f, -0.18703481171888114f,
                               -0.02798376941698385f,  0.6308807679295904f,
                                0.7148465705525415f,   0.23037781330885523f };
__constant__ float c_hi[8] = { -0.23037781330885523f,  0.7148465705525415f,
                               -0.6308807679295904f,  -0.02798376941698385f,
                                0.18703481171888114f,  0.030841381835986965f,
                               -0.032883011666982945f, -0.010597401784997278f };

__device__ __forceinline__ uint32_t f2tf32(float f) {
    uint32_t u;
    asm("cvt.rna.tf32.f32 %0, %1;" : "=r"(u) : "f"(f));
    return u;
}

__device__ __forceinline__ void mma_tf32(float& d0, float& d1, float& d2, float& d3,
                                         uint32_t a0, uint32_t a1, uint32_t a2, uint32_t a3,
                                         uint32_t b0, uint32_t b1) {
    asm volatile(
        "mma.sync.aligned.m16n8k8.row.col.f32.tf32.tf32.f32 "
        "{%0,%1,%2,%3}, {%4,%5,%6,%7}, {%8,%9}, {%0,%1,%2,%3};"
        : "+f"(d0), "+f"(d1), "+f"(d2), "+f"(d3)
        : "r"(a0), "r"(a1), "r"(a2), "r"(a3), "r"(b0), "r"(b1));
}

__device__ __forceinline__ void mma_f16(float& d0, float& d1, float& d2, float& d3,
                                        uint32_t a0, uint32_t a1, uint32_t a2, uint32_t a3,
                                        uint32_t b0, uint32_t b1) {
    asm volatile(
        "mma.sync.aligned.m16n8k16.row.col.f32.f16.f16.f32 "
        "{%0,%1,%2,%3}, {%4,%5,%6,%7}, {%8,%9}, {%0,%1,%2,%3};"
        : "+f"(d0), "+f"(d1), "+f"(d2), "+f"(d3)
        : "r"(a0), "r"(a1), "r"(a2), "r"(a3), "r"(b0), "r"(b1));
}

// split fp32 pair -> fp16 hi pair + fp16 lo (residual) pair, packed as b32
__device__ __forceinline__ void split_h2(float x, float y, uint32_t& hi, uint32_t& lo) {
    __half2 h = __float22half2_rn(make_float2(x, y));
    float2 b = __half22float2(h);
    __half2 l = __float22half2_rn(make_float2(x - b.x, y - b.y));
    hi = *(uint32_t*)&h;
    lo = *(uint32_t*)&l;
}

// ======================================================================
// Kernel 1: QKV projection via mma.sync tf32; V-epilogue fuses db4 DWT.
// __launch_bounds__(256, 2): cap regs so 2 CTAs/SM are resident.
// ======================================================================
#define CHN 4608            // 128*36 floats per buffer
#define QKV_SMEM (4*CHN*4)  // As[2] + Bs[2] = 73728 bytes (>= 128*132 floats too)

__global__ __launch_bounds__(256, 2) void qkv_mma_kernel(
    const float* __restrict__ x, const float* __restrict__ Wq,
    const float* __restrict__ Wk, const float* __restrict__ Wv,
    float* __restrict__ out2)
{
    extern __shared__ float sm[];
    float* As = sm;             // [2][128][36]
    float* Bs = sm + 2*CHN;     // [2][128][36]

    const int tid  = threadIdx.x;
    const int lane = tid & 31;
    const int warp = tid >> 5;
    const int g    = lane >> 2;
    const int tig  = lane & 3;
    const int wm   = warp & 3;
    const int wn   = warp >> 2;

    const int which = blockIdx.z;
    const float* W = (which == 0) ? Wq : ((which == 1) ? Wk : Wv);
    const float scale = (which == 0) ? 0.08838834764831845f : 1.0f;

    const int m0   = blockIdx.y * 128;
    const int head = blockIdx.x;
    const float* xb = x + (size_t)m0 * 1024;
    const float* wb = W + (size_t)head * 128 * 1024;

    const int lr = tid >> 3;
    const int lc = (tid & 7) * 4;

    float c[2][8][4];
#pragma unroll
    for (int mt = 0; mt < 2; mt++)
#pragma unroll
        for (int nt = 0; nt < 8; nt++)
#pragma unroll
            for (int q = 0; q < 4; q++) c[mt][nt][q] = 0.0f;

    {
#pragma unroll
        for (int u = 0; u < 4; u++) {
            const int r = lr + 32*u;
            const float4 a4 = *(const float4*)(xb + (size_t)r*1024 + lc);
            const float4 b4 = *(const float4*)(wb + (size_t)r*1024 + lc);
            float* pa = As + r*36 + lc;
            float* pb = Bs + r*36 + lc;
            pa[0] = __uint_as_float(f2tf32(a4.x)); pa[1] = __uint_as_float(f2tf32(a4.y));
            pa[2] = __uint_as_float(f2tf32(a4.z)); pa[3] = __uint_as_float(f2tf32(a4.w));
            pb[0] = __uint_as_float(f2tf32(b4.x)); pb[1] = __uint_as_float(f2tf32(b4.y));
            pb[2] = __uint_as_float(f2tf32(b4.z)); pb[3] = __uint_as_float(f2tf32(b4.w));
        }
    }
    __syncthreads();

    for (int ch = 0; ch < 32; ch++) {
        const int cur = ch & 1;
        float4 pfa[4], pfb[4];
        if (ch < 31) {
            const int kb = (ch + 1) << 5;
#pragma unroll
            for (int u = 0; u < 4; u++) {
                const int r = lr + 32*u;
                pfa[u] = *(const float4*)(xb + (size_t)r*1024 + kb + lc);
                pfb[u] = *(const float4*)(wb + (size_t)r*1024 + kb + lc);
            }
        }

        const float* as = As + cur*CHN;
        const float* bs = Bs + cur*CHN;
#pragma unroll
        for (int ks = 0; ks < 4; ks++) {
            const int k0 = ks * 8;
            uint32_t a[2][4];
#pragma unroll
            for (int mt = 0; mt < 2; mt++) {
                const int rb = wm*32 + mt*16 + g;
                a[mt][0] = __float_as_uint(as[(rb    )*36 + k0 + tig]);
                a[mt][1] = __float_as_uint(as[(rb + 8)*36 + k0 + tig]);
                a[mt][2] = __float_as_uint(as[(rb    )*36 + k0 + tig + 4]);
                a[mt][3] = __float_as_uint(as[(rb + 8)*36 + k0 + tig + 4]);
            }
#pragma unroll
            for (int nt = 0; nt < 8; nt++) {
                const int nb = wn*64 + nt*8 + g;
                const uint32_t b0 = __float_as_uint(bs[nb*36 + k0 + tig]);
                const uint32_t b1 = __float_as_uint(bs[nb*36 + k0 + tig + 4]);
#pragma unroll
                for (int mt = 0; mt < 2; mt++)
                    mma_tf32(c[mt][nt][0], c[mt][nt][1], c[mt][nt][2], c[mt][nt][3],
                             a[mt][0], a[mt][1], a[mt][2], a[mt][3], b0, b1);
            }
        }

        if (ch < 31) {
            float* pa0 = As + (cur^1)*CHN;
            float* pb0 = Bs + (cur^1)*CHN;
#pragma unroll
            for (int u = 0; u < 4; u++) {
                const int r = lr + 32*u;
                float* pa = pa0 + r*36 + lc;
                float* pb = pb0 + r*36 + lc;
                pa[0] = __uint_as_float(f2tf32(pfa[u].x)); pa[1] = __uint_as_float(f2tf32(pfa[u].y));
                pa[2] = __uint_as_float(f2tf32(pfa[u].z)); pa[3] = __uint_as_float(f2tf32(pfa[u].w));
                pb[0] = __uint_as_float(f2tf32(pfb[u].x)); pb[1] = __uint_as_float(f2tf32(pfb[u].y));
                pb[2] = __uint_as_float(f2tf32(pfb[u].z)); pb[3] = __uint_as_float(f2tf32(pfb[u].w));
            }
        }
        __syncthreads();
    }

    if (which < 2) {
        // ---- Q/K epilogue: write (b,h,s,d), scale for Q ----
        float* O = (which == 0) ? g_Q : g_K;
#pragma unroll
        for (int mt = 0; mt < 2; mt++) {
            const int m  = m0 + wm*32 + mt*16 + g;
            const int b0_ = m >> 11, sq = m & 2047;
            float* dst0 = O + (((size_t)(b0_*8 + head) * 2048 + sq) << 7);
            float* dst1 = dst0 + (8 << 7);
#pragma unroll
            for (int nt = 0; nt < 8; nt++) {
                const int d = wn*64 + nt*8 + 2*tig;
                float2 v0 = make_float2(c[mt][nt][0]*scale, c[mt][nt][1]*scale);
                float2 v1 = make_float2(c[mt][nt][2]*scale, c[mt][nt][3]*scale);
                *(float2*)(dst0 + d) = v0;
                *(float2*)(dst1 + d) = v1;
            }
        }
    } else {
        // ---- V epilogue: stage tile in SMEM, fused db4 DWT ----
        float* Vt = sm;           // [128][132]
#pragma unroll
        for (int mt = 0; mt < 2; mt++) {
            const int r0 = wm*32 + mt*16 + g;
#pragma unroll
            for (int nt = 0; nt < 8; nt++) {
                const int d = wn*64 + nt*8 + 2*tig;
                *(float2*)(Vt + (r0    )*132 + d) = make_float2(c[mt][nt][0], c[mt][nt][1]);
                *(float2*)(Vt + (r0 + 8)*132 + d) = make_float2(c[mt][nt][2], c[mt][nt][3]);
            }
        }
        __syncthreads();
        // 2 threads per row; each handles interleaved t values
        const int r    = tid >> 1;
        const int half = tid & 1;
        const int m    = m0 + r;
        const int b0_  = m >> 11, sq = m & 2047;
        const size_t rowbase = ((size_t)(b0_*8 + head) * 2048 + sq) * WAW;
        const float* v = Vt + r*132;
        for (int t = half; t < WAW; t += 2) {
            float a = 0.0f, d = 0.0f;
#pragma unroll
            for (int k = 0; k < 8; k++) {
                const int j = 2*t + k;
                const int src = (j < 6) ? (5 - j) : ((j < 134) ? (j - 6) : (261 - j));
                const float e = v[src];
                a = fmaf(e, c_lo[7 - k], a);
                d = fmaf(e, c_hi[7 - k], d);
            }
            out2[rowbase + t] = a;
            g_cD[rowbase + t] = d;
        }
    }
}

// ======================================================================
// Kernel 3: flash attention fused with (attn @ cD).
// fp16 hi/lo split (Markidis, 3 MMAs m16n8k16) == fp32-grade accuracy.
// (unchanged from R5 pass)
// ======================================================================
#define SH68   68                 // b32 stride per row
#define QT_B32 (128*SH68)         // 8704 b32 per 128-row tile
#define FL_SMEM ((4*QT_B32 + 2*72*SH68 + 896) * 4)   // 182016 B

__global__ __launch_bounds__(256, 1) void flash_f16_kernel(float* __restrict__ out1)
{
    extern __shared__ __align__(16) uint32_t smw[];
    uint32_t* Qhi  = smw;                   // [128][68]
    uint32_t* Qlo  = Qhi + QT_B32;
    uint32_t* Khi  = Qlo + QT_B32;          // aliased as Phi
    uint32_t* Klo  = Khi + QT_B32;          // aliased as Plo
    uint32_t* cDhi = Klo + QT_B32;          // [72][68]  (transposed: [w][key])
    uint32_t* cDlo = cDhi + 72*SH68;
    float* rmax = (float*)(cDlo + 72*SH68); // [128][2]
    float* rsum = rmax + 256;               // [128][2]
    float* m_s  = rsum + 256;               // [128]
    float* l_s  = m_s + 128;                // [128]
    float* al_s = l_s + 128;                // [128]

    const int tid  = threadIdx.x;
    const int lane = tid & 31;
    const int warp = tid >> 5;
    const int g    = lane >> 2;
    const int tig  = lane & 3;
    const int wm   = warp & 3;
    const int wn   = warp >> 2;

    const int bh = blockIdx.y;
    const int q0 = blockIdx.x * 128;
    const float* Qg  = g_Q  + (size_t)bh * SEQ * DKD;
    const float* Kg  = g_K  + (size_t)bh * SEQ * DKD;
    const float* cDg = g_cD + (size_t)bh * SEQ * WAW;

    // ---- load + split Q (once) ----
#pragma unroll
    for (int u = 0; u < 16; u++) {
        const int idx = tid + 256*u;
        const int r = idx >> 5, c4 = idx & 31;
        const float4 q4 = *(const float4*)(Qg + (size_t)(q0 + r)*DKD + c4*4);
        uint32_t h0, l0, h1, l1;
        split_h2(q4.x, q4.y, h0, l0);
        split_h2(q4.z, q4.w, h1, l1);
        Qhi[r*SH68 + 2*c4]     = h0;  Qhi[r*SH68 + 2*c4 + 1] = h1;
        Qlo[r*SH68 + 2*c4]     = l0;  Qlo[r*SH68 + 2*c4 + 1] = l1;
    }
    // zero cD pad rows 67..71
    for (int i = tid; i < 5*SH68; i += 256) {
        cDhi[67*SH68 + i] = 0;
        cDlo[67*SH68 + i] = 0;
    }
    if (tid < 128) { m_s[tid] = -1e30f; l_s[tid] = 0.0f; }

    float o[9][4];
#pragma unroll
    for (int nt = 0; nt < 9; nt++)
#pragma unroll
        for (int q = 0; q < 4; q++) o[nt][q] = 0.0f;

    __syncthreads();

    for (int kt = 0; kt < 16; kt++) {
        const int n0 = kt * 128;
        // ---- load + split K tile ----
#pragma unroll
        for (int u = 0; u < 16; u++) {
            const int idx = tid + 256*u;
            const int r = idx >> 5, c4 = idx & 31;
            const float4 k4 = *(const float4*)(Kg + (size_t)(n0 + r)*DKD + c4*4);
            uint32_t h0, l0, h1, l1;
            split_h2(k4.x, k4.y, h0, l0);
            split_h2(k4.z, k4.w, h1, l1);
            Khi[r*SH68 + 2*c4]     = h0;  Khi[r*SH68 + 2*c4 + 1] = h1;
            Klo[r*SH68 + 2*c4]     = l0;  Klo[r*SH68 + 2*c4 + 1] = l1;
        }
        // ---- load + split cD tile, TRANSPOSED: [w][key pairs] ----
#pragma unroll
        for (int u = 0; u < 16; u++) {
            const int idx = tid + 256*u;
            const int j2 = idx >> 6, w = idx & 63;
            const float v0 = cDg[(size_t)(n0 + 2*j2    )*WAW + w];
            const float v1 = cDg[(size_t)(n0 + 2*j2 + 1)*WAW + w];
            uint32_t h, l;
            split_h2(v0, v1, h, l);
            cDhi[w*SH68 + j2] = h;
            cDlo[w*SH68 + j2] = l;
        }
        {   // tail: w = 64..66
            const int wt = tid & 3, j2 = tid >> 2;
            if (wt < 3) {
                const int w = 64 + wt;
                const float v0 = cDg[(size_t)(n0 + 2*j2    )*WAW + w];
                const float v1 = cDg[(size_t)(n0 + 2*j2 + 1)*WAW + w];
                uint32_t h, l;
                split_h2(v0, v1, h, l);
                cDhi[w*SH68 + j2] = h;
                cDlo[w*SH68 + j2] = l;
            }
        }
        __syncthreads();

        // ---- S = Q K^T : fp16 hi/lo, 3 MMAs per fragment ----
        float s[2][8][4];
#pragma unroll
        for (int mt = 0; mt < 2; mt++)
#pragma unroll
            for (int nt = 0; nt < 8; nt++)
#pragma unroll
                for (int q = 0; q < 4; q++) s[mt][nt][q] = 0.0f;

#pragma unroll 2
        for (int ks = 0; ks < 8; ks++) {
            const int k0b = ks * 8;
            uint32_t ah[2][4], al_[2][4];
#pragma unroll
            for (int mt = 0; mt < 2; mt++) {
                const int rb = wm*32 + mt*16 + g;
                ah[mt][0] = Qhi[(rb    )*SH68 + k0b + tig];
                ah[mt][1] = Qhi[(rb + 8)*SH68 + k0b + tig];
                ah[mt][2] = Qhi[(rb    )*SH68 + k0b + tig + 4];
                ah[mt][3] = Qhi[(rb + 8)*SH68 + k0b + tig + 4];
                al_[mt][0] = Qlo[(rb    )*SH68 + k0b + tig];
                al_[mt][1] = Qlo[(rb + 8)*SH68 + k0b + tig];
                al_[mt][2] = Qlo[(rb    )*SH68 + k0b + tig + 4];
                al_[mt][3] = Qlo[(rb + 8)*SH68 + k0b + tig + 4];
            }
#pragma unroll
            for (int nt = 0; nt < 8; nt++) {
                const int nb = wn*64 + nt*8 + g;
                const uint32_t bh0 = Khi[nb*SH68 + k0b + tig];
                const uint32_t bh1 = Khi[nb*SH68 + k0b + tig + 4];
                const uint32_t bl0 = Klo[nb*SH68 + k0b + tig];
                const uint32_t bl1 = Klo[nb*SH68 + k0b + tig + 4];
#pragma unroll
                for (int mt = 0; mt < 2; mt++) {
                    mma_f16(s[mt][nt][0], s[mt][nt][1], s[mt][nt][2], s[mt][nt][3],
                            ah[mt][0], ah[mt][1], ah[mt][2], ah[mt][3], bh0, bh1);
                    mma_f16(s[mt][nt][0], s[mt][nt][1], s[mt][nt][2], s[mt][nt][3],
                            ah[mt][0], ah[mt][1], ah[mt][2], ah[mt][3], bl0, bl1);
                    mma_f16(s[mt][nt][0], s[mt][nt][1], s[mt][nt][2], s[mt][nt][3],
                            al_[mt][0], al_[mt][1], al_[mt][2], al_[mt][3], bh0, bh1);
                }
            }
        }

        // ---- row max (quad shfl + cross-warp SMEM) ----
        float mx[2][2];
#pragma unroll
        for (int mt = 0; mt < 2; mt++)
#pragma unroll
            for (int hf = 0; hf < 2; hf++) {
                float m = -1e30f;
#pragma unroll
                for (int nt = 0; nt < 8; nt++)
                    m = fmaxf(m, fmaxf(s[mt][nt][2*hf], s[mt][nt][2*hf+1]));
                m = fmaxf(m, __shfl_xor_sync(0xffffffffu, m, 1));
                m = fmaxf(m, __shfl_xor_sync(0xffffffffu, m, 2));
                mx[mt][hf] = m;
            }
        if (tig == 0) {
#pragma unroll
            for (int mt = 0; mt < 2; mt++)
#pragma unroll
                for (int hf = 0; hf < 2; hf++) {
                    const int row = wm*32 + mt*16 + g + 8*hf;
                    rmax[row*2 + wn] = mx[mt][hf];
                }
        }
        __syncthreads();

        float mnew[2][2], alv[2][2], ssum[2][2];
#pragma unroll
        for (int mt = 0; mt < 2; mt++)
#pragma unroll
            for (int hf = 0; hf < 2; hf++) {
                const int row = wm*32 + mt*16 + g + 8*hf;
                const float tm = fmaxf(rmax[row*2], rmax[row*2+1]);
                const float mo = m_s[row];
                const float mn = fmaxf(mo, tm);
                mnew[mt][hf] = mn;
                alv[mt][hf]  = __expf(mo - mn);
                ssum[mt][hf] = 0.0f;
            }
#pragma unroll
        for (int mt = 0; mt < 2; mt++) {
            const int r0 = wm*32 + mt*16 + g;
#pragma unroll
            for (int nt = 0; nt < 8; nt++) {
                const int cb = 32*wn + 4*nt + tig;     // b32 col
                float p0 = __expf(s[mt][nt][0] - mnew[mt][0]);
                float p1 = __expf(s[mt][nt][1] - mnew[mt][0]);
                float p2 = __expf(s[mt][nt][2] - mnew[mt][1]);
                float p3 = __expf(s[mt][nt][3] - mnew[mt][1]);
                ssum[mt][0] += p0 + p1;
                ssum[mt][1] += p2 + p3;
                uint32_t h, l;
                split_h2(p0, p1, h, l);
                Khi[(r0    )*SH68 + cb] = h;   // Phi
                Klo[(r0    )*SH68 + cb] = l;   // Plo
                split_h2(p2, p3, h, l);
                Khi[(r0 + 8)*SH68 + cb] = h;
                Klo[(r0 + 8)*SH68 + cb] = l;
            }
        }
#pragma unroll
        for (int mt = 0; mt < 2; mt++)
#pragma unroll
            for (int hf = 0; hf < 2; hf++) {
                float sv = ssum[mt][hf];
                sv += __shfl_xor_sync(0xffffffffu, sv, 1);
                sv += __shfl_xor_sync(0xffffffffu, sv, 2);
                if (tig == 0) {
                    const int row = wm*32 + mt*16 + g + 8*hf;
                    rsum[row*2 + wn] = sv;
                }
            }
        __syncthreads();

        if (wn == 0 && tig == 0) {
#pragma unroll
            for (int mt = 0; mt < 2; mt++)
#pragma unroll
                for (int hf = 0; hf < 2; hf++) {
                    const int row = wm*32 + mt*16 + g + 8*hf;
                    const float ts = rsum[row*2] + rsum[row*2+1];
                    l_s[row]  = l_s[row]*alv[mt][hf] + ts;
                    m_s[row]  = mnew[mt][hf];
                    al_s[row] = alv[mt][hf];
                }
        }
        __syncthreads();

        // ---- PV: o += P @ cD^T, fp16 hi/lo 3-MMA ----
        {
            const int rb = warp*16 + g;
            const float a0 = al_s[rb], a1 = al_s[rb + 8];
#pragma unroll
            for (int nt = 0; nt < 9; nt++) {
                o[nt][0] *= a0; o[nt][1] *= a0;
                o[nt][2] *= a1; o[nt][3] *= a1;
            }
#pragma unroll 2
            for (int ks = 0; ks < 8; ks++) {
                const int k0b = ks * 8;
                uint32_t ph[4], pl[4];
                ph[0] = Khi[(rb    )*SH68 + k0b + tig];
                ph[1] = Khi[(rb + 8)*SH68 + k0b + tig];
                ph[2] = Khi[(rb    )*SH68 + k0b + tig + 4];
                ph[3] = Khi[(rb + 8)*SH68 + k0b + tig + 4];
                pl[0] = Klo[(rb    )*SH68 + k0b + tig];
                pl[1] = Klo[(rb + 8)*SH68 + k0b + tig];
                pl[2] = Klo[(rb    )*SH68 + k0b + tig + 4];
                pl[3] = Klo[(rb + 8)*SH68 + k0b + tig + 4];
#pragma unroll
                for (int nt = 0; nt < 9; nt++) {
                    const int wr = nt*8 + g;
                    const uint32_t ch0 = cDhi[wr*SH68 + k0b + tig];
                    const uint32_t ch1 = cDhi[wr*SH68 + k0b + tig + 4];
                    const uint32_t cl0 = cDlo[wr*SH68 + k0b + tig];
                    const uint32_t cl1 = cDlo[wr*SH68 + k0b + tig + 4];
                    mma_f16(o[nt][0], o[nt][1], o[nt][2], o[nt][3],
                            ph[0], ph[1], ph[2], ph[3], ch0, ch1);
                    mma_f16(o[nt][0], o[nt][1], o[nt][2], o[nt][3],
                            ph[0], ph[1], ph[2], ph[3], cl0, cl1);
                    mma_f16(o[nt][0], o[nt][1], o[nt][2], o[nt][3],
                            pl[0], pl[1], pl[2], pl[3], ch0, ch1);
                }
            }
        }
        __syncthreads();
    }

    // ---- epilogue ----
    const int rb = warp*16 + g;
    const float inv0 = 1.0f / l_s[rb];
    const float inv1 = 1.0f / l_s[rb + 8];
    const int b = bh >> 3, h = bh & 7;
    const size_t base0 = (size_t)(b*2048 + q0 + rb) * 536 + h*67;
    const size_t base1 = base0 + (size_t)8 * 536;
#pragma unroll
    for (int nt = 0; nt < 9; nt++) {
        const int col = nt*8 + 2*tig;
        if (col < WAW) {
            out1[base0 + col] = o[nt][0] * inv0;
            out1[base1 + col] = o[nt][2] * inv1;
        }
        if (col + 1 < WAW) {
            out1[base0 + col + 1] = o[nt][1] * inv0;
            out1[base1 + col + 1] = o[nt][3] * inv1;
        }
    }
}

// ======================================================================
extern "C" void kernel_launch(void* const* d_in, const int* in_sizes, int n_in,
                              void* d_out, int out_size)
{
    (void)in_sizes; (void)n_in; (void)out_size;
    const float* x  = (const float*)d_in[0];
    const float* Wq = (const float*)d_in[1];
    const float* Wk = (const float*)d_in[2];
    const float* Wv = (const float*)d_in[3];
    float* out = (float*)d_out;

    cudaFuncSetAttribute(qkv_mma_kernel, cudaFuncAttributeMaxDynamicSharedMemorySize,
                         QKV_SMEM);
    qkv_mma_kernel<<<dim3(8, 64, 3), 256, QKV_SMEM>>>(x, Wq, Wk, Wv,
                                                      out + OUT1_ELEMS);

    cudaFuncSetAttribute(flash_f16_kernel, cudaFuncAttributeMaxDynamicSharedMemorySize,
                         FL_SMEM);
    flash_f16_kernel<<<dim3(16, 32), 256, FL_SMEM>>>(out);
}